// round 6
// baseline (speedup 1.0000x reference)
#include <cuda_runtime.h>
#include <cuda_fp16.h>
#include <cstdint>

// ---------------- problem dims ----------------
#define Bb   8
#define Tt   4
#define Nn   256
#define Dd   512
#define Hh   8
#define DHh  64
#define HIDd 2048
#define BTN  (Bb*Tt*Nn)            // 8192 rows
#define BTND ((size_t)BTN*Dd)      // 4194304
#define SCORES_ELEMS ((size_t)Bb*Tt*Hh*Nn*Nn)  // 16777216
#define HID_ELEMS    ((size_t)BTN*HIDd)        // 16777216
#define QKVW (3*Dd)                // 1536

#define BETA 0.95122942450071403f  // fp32(exp(-1/20))
#define LOSCALE 2048.0f
#define INV_LOSCALE (1.0f/2048.0f)

// ---------------- scratch (static device globals; no allocation) ----------------
__device__ __half g_s1h[BTND];
__device__ __half g_qkvh[(size_t)BTN*QKVW], g_qkvl[(size_t)BTN*QKVW];
__device__ float  g_scores[SCORES_ELEMS];
__device__ __half g_sah[SCORES_ELEMS];
__device__ __half g_aoh[BTND], g_aol[BTND];
__device__ float  g_xm[BTND];
__device__ __half g_s2h[BTND];
__device__ float  g_hid[HID_ELEMS];
__device__ __half g_hsh[HID_ELEMS];
// weight splits
__device__ __half g_wqkvh[Dd*QKVW], g_wqkvl[Dd*QKVW];
__device__ __half g_woh[Dd*Dd], g_wol[Dd*Dd];
__device__ __half g_w1h[Dd*HIDd], g_w1l[Dd*HIDd];
__device__ __half g_w2h[HIDd*Dd], g_w2l[HIDd*Dd];
__device__ unsigned long long g_cnt[4];

// ---------------- small helpers ----------------
__global__ void zero_cnt_kernel() {
    if (threadIdx.x < 4) g_cnt[threadIdx.x] = 0ULL;
}

__global__ void split_kernel(const float* __restrict__ src,
                             __half* __restrict__ hi, __half* __restrict__ lo, int n) {
    int i = blockIdx.x*blockDim.x + threadIdx.x;
    if (i < n) {
        float v = src[i];
        __half h = __float2half_rn(v);
        hi[i] = h;
        lo[i] = __float2half_rn((v - __half2float(h)) * LOSCALE);
    }
}

// split wq/wk/wv [512x512] into concatenated [512 x 1536] hi/lo
__global__ void split_qkv_kernel(const float* __restrict__ wq,
                                 const float* __restrict__ wk,
                                 const float* __restrict__ wv,
                                 __half* __restrict__ hi, __half* __restrict__ lo) {
    int i = blockIdx.x*blockDim.x + threadIdx.x;   // 0 .. 3*512*512-1
    int which = i / (Dd*Dd);
    int rem = i % (Dd*Dd);
    int r = rem / Dd, c = rem % Dd;
    const float* src = (which == 0) ? wq : (which == 1) ? wk : wv;
    float v = src[rem];
    __half h = __float2half_rn(v);
    size_t off = (size_t)r*QKVW + which*Dd + c;
    hi[off] = h;
    lo[off] = __float2half_rn((v - __half2float(h)) * LOSCALE);
}

// ---------------- block reduction (512 threads) ----------------
__device__ __forceinline__ float block_sum(float v, float* red) {
    int lane = threadIdx.x & 31, w = threadIdx.x >> 5;
    #pragma unroll
    for (int off = 16; off; off >>= 1) v += __shfl_down_sync(0xffffffffu, v, off);
    __syncthreads();
    if (lane == 0) red[w] = v;
    __syncthreads();
    if (threadIdx.x < 32) {
        float t = (threadIdx.x < 16) ? red[threadIdx.x] : 0.f;
        #pragma unroll
        for (int off = 8; off; off >>= 1) t += __shfl_down_sync(0xffffffffu, t, off);
        if (threadIdx.x == 0) red[32] = t;
    }
    __syncthreads();
    return red[32];
}

// ---------------- LayerNorm + LIF over time (per (b,n) row) ----------------
__global__ void ln_lif_kernel(const float* __restrict__ x,
                              const float* __restrict__ g,
                              const float* __restrict__ bia,
                              __half* __restrict__ sp,
                              unsigned long long* __restrict__ counter) {
    __shared__ float red[33];
    int bn = blockIdx.x;
    int b  = bn / Nn, n = bn % Nn;
    int d  = threadIdx.x;
    float gg = g[d], bb = bia[d];
    float mem = 0.f;
    float cnt = 0.f;
    for (int t = 0; t < Tt; ++t) {
        size_t rowoff = ((((size_t)b*Tt + t)*Nn) + n)*Dd;
        float v = x[rowoff + d];
        float mean = block_sum(v, red) * (1.f/Dd);
        float diff = v - mean;
        float var = block_sum(diff*diff, red) * (1.f/Dd);
        float h = diff * rsqrtf(var + 1e-5f) * gg + bb;
        mem = BETA*mem + h;
        float s = (mem >= 1.0f) ? 1.f : 0.f;
        mem -= s;
        sp[rowoff + d] = __float2half_rn(s);
        cnt += s;
    }
    float tot = block_sum(cnt, red);
    if (d == 0) atomicAdd(counter, (unsigned long long)(tot + 0.5f));
}

// ---------------- LIF over time axis: fp32 src -> binary fp16 spikes ----------------
__global__ void lif_time_kernel(const float* __restrict__ src, __half* __restrict__ dst,
                                int inner_sz, float thr,
                                unsigned long long* __restrict__ counter) {
    long long total = (long long)Bb * inner_sz;
    long long idx = (long long)blockIdx.x*blockDim.x + threadIdx.x;
    int cnt = 0;
    if (idx < total) {
        long long b = idx / inner_sz, r = idx % inner_sz;
        const float* p = src + (size_t)b*Tt*inner_sz + r;
        __half* q = dst + (size_t)b*Tt*inner_sz + r;
        float mem = 0.f;
        #pragma unroll
        for (int t = 0; t < Tt; ++t) {
            float v2 = p[(size_t)t*inner_sz];
            mem = BETA*mem + v2;
            float s = (mem >= thr) ? 1.f : 0.f;
            q[(size_t)t*inner_sz] = __float2half_rn(s);
            mem -= s*thr;
            cnt += (int)s;
        }
    }
    #pragma unroll
    for (int off = 16; off; off >>= 1) cnt += __shfl_down_sync(0xffffffffu, cnt, off);
    if ((threadIdx.x & 31) == 0 && cnt) atomicAdd(counter, (unsigned long long)cnt);
}

// ---------------- fp16 MMA primitives ----------------
__device__ __forceinline__ uint32_t cvta_sh(const void* p) {
    return (uint32_t)__cvta_generic_to_shared(p);
}
__device__ __forceinline__ void ldsm4(uint32_t* r, uint32_t addr) {
    asm volatile("ldmatrix.sync.aligned.m8n8.x4.shared.b16 {%0,%1,%2,%3}, [%4];\n"
        : "=r"(r[0]), "=r"(r[1]), "=r"(r[2]), "=r"(r[3]) : "r"(addr));
}
__device__ __forceinline__ void ldsm4t(uint32_t* r, uint32_t addr) {
    asm volatile("ldmatrix.sync.aligned.m8n8.x4.trans.shared.b16 {%0,%1,%2,%3}, [%4];\n"
        : "=r"(r[0]), "=r"(r[1]), "=r"(r[2]), "=r"(r[3]) : "r"(addr));
}
__device__ __forceinline__ void mma16816(float* c, const uint32_t* a, const uint32_t* b) {
    asm volatile("mma.sync.aligned.m16n8k16.row.col.f32.f16.f16.f32 "
        "{%0,%1,%2,%3},{%4,%5,%6,%7},{%8,%9},{%0,%1,%2,%3};\n"
        : "+f"(c[0]), "+f"(c[1]), "+f"(c[2]), "+f"(c[3])
        : "r"(a[0]), "r"(a[1]), "r"(a[2]), "r"(a[3]), "r"(b[0]), "r"(b[1]));
}
__device__ __forceinline__ void cp16(void* smem, const void* gmem) {
    asm volatile("cp.async.cg.shared.global [%0], [%1], 16;\n"
        :: "r"(cvta_sh(smem)), "l"(gmem));
}
#define CP_COMMIT() asm volatile("cp.async.commit_group;\n")
#define CP_WAIT0()  asm volatile("cp.async.wait_group 0;\n")

// ---------------- generic split-fp16 MMA GEMM, cp.async double-buffered ----------------
// C = (Ahi@Bhi + 2^-11*(Ahi@Blo [+ Alo@Bhi])) * outscale [+ R]
// Block tile 128 x TN (TN=128 or 64), BK=32, 256 threads (8 warps, 4x2 warp grid,
// warp tile 32 x TN/2).
// BT=true : B is k-major [K x N] row-major (standard GEMM), ldmatrix.trans
// BT=false: B is n-major [N x K] row-major (C = A@B^T), ldmatrix
template<bool HAS_ALO, bool BT, bool SPLIT_OUT, bool HAS_RES, int TN>
__global__ void __launch_bounds__(256, 1)
mma_gemm(const __half* __restrict__ Ah, const __half* __restrict__ Al,
         const __half* __restrict__ Bh, const __half* __restrict__ Bl,
         const float* __restrict__ R, float* __restrict__ Cf,
         __half* __restrict__ Ch, __half* __restrict__ Cl,
         int K, int lda, int ldb, int ldc,
         int zdiv,
         long long sA1, long long sA2,
         long long sB1, long long sB2,
         long long sC1, long long sC2,
         float outscale)
{
    extern __shared__ __half sm[];
    constexpr int AH_SZ  = 128*40;                          // 5120 halves
    constexpr int A_SZ   = HAS_ALO ? 2*AH_SZ : AH_SZ;
    constexpr int BPITCH = BT ? (TN + 8) : 40;
    constexpr int B_SZ   = BT ? 32*BPITCH : TN*40;          // per hi/lo tile
    constexpr int STAGE  = A_SZ + 2*B_SZ;
    constexpr int WN     = TN/2;                            // per-warp N width
    constexpr int NH     = WN/16;                           // 16-col ldsm groups
    constexpr int NJ     = 2*NH;                            // 8-col mma tiles
    constexpr int BCHUNK_ITERS = (32*TN/8)/256;             // 2 (TN=128) or 1 (TN=64)

    int tid = threadIdx.x, lane = tid & 31, wid = tid >> 5;
    int wm = (wid & 3) * 32, wn = (wid >> 2) * WN;
    int bm0 = blockIdx.y * 128, bn0 = blockIdx.x * TN;
    int z = blockIdx.z, z1 = z / zdiv, z2 = z % zdiv;
    size_t aoff = (size_t)z1*sA1 + (size_t)z2*sA2;
    size_t boff = (size_t)z1*sB1 + (size_t)z2*sB2;
    size_t coff = (size_t)z1*sC1 + (size_t)z2*sC2;

    float acc0[2][NJ][4] = {};
    float acc1[2][NJ][4] = {};

    auto load_stage = [&](int k0, int st) {
        __half* base = sm + st*STAGE;
        #pragma unroll
        for (int i = 0; i < 2; i++) {                    // 512 A chunks of 8 halves
            int idx = tid + i*256;
            int row = idx >> 2, col = (idx & 3) << 3;
            cp16(&base[row*40 + col],
                 Ah + aoff + (size_t)(bm0+row)*lda + k0 + col);
            if (HAS_ALO)
                cp16(&base[AH_SZ + row*40 + col],
                     Al + aoff + (size_t)(bm0+row)*lda + k0 + col);
        }
        __half* sBh = base + A_SZ;
        __half* sBl = sBh + B_SZ;
        #pragma unroll
        for (int i = 0; i < BCHUNK_ITERS; i++) {
            int idx = tid + i*256;
            if (BT) {
                int row = idx / (TN/8), col = (idx % (TN/8)) << 3;   // 32 x TN
                cp16(&sBh[row*BPITCH + col], Bh + boff + (size_t)(k0+row)*ldb + bn0 + col);
                cp16(&sBl[row*BPITCH + col], Bl + boff + (size_t)(k0+row)*ldb + bn0 + col);
            } else {
                int row = idx >> 2, col = (idx & 3) << 3;            // TN x 32
                cp16(&sBh[row*40 + col], Bh + boff + (size_t)(bn0+row)*ldb + k0 + col);
                cp16(&sBl[row*40 + col], Bl + boff + (size_t)(bn0+row)*ldb + k0 + col);
            }
        }
        CP_COMMIT();
    };

    load_stage(0, 0);

    int st = 0;
    for (int k0 = 0; k0 < K; k0 += 32, st ^= 1) {
        CP_WAIT0();
        __syncthreads();
        if (k0 + 32 < K) load_stage(k0 + 32, st ^ 1);

        __half* base = sm + st*STAGE;
        __half* sAh = base;
        __half* sAl = base + AH_SZ;
        __half* sBh = base + A_SZ;
        __half* sBl = sBh + B_SZ;

        #pragma unroll
        for (int kk = 0; kk < 32; kk += 16) {
            uint32_t afh[2][4], afl[2][4];
            #pragma unroll
            for (int mi = 0; mi < 2; mi++) {
                int row = wm + mi*16 + (lane & 15);
                int col = kk + ((lane >> 4) << 3);
                ldsm4(afh[mi], cvta_sh(&sAh[row*40 + col]));
                if (HAS_ALO) ldsm4(afl[mi], cvta_sh(&sAl[row*40 + col]));
            }
            uint32_t bfh[NH][4], bfl[NH][4];
            int g = lane >> 3, rr = lane & 7;
            #pragma unroll
            for (int nh = 0; nh < NH; nh++) {
                if (BT) {
                    int krow = kk + (g & 1)*8 + rr;
                    int ncol = wn + nh*16 + (g >> 1)*8;
                    ldsm4t(bfh[nh], cvta_sh(&sBh[krow*BPITCH + ncol]));
                    ldsm4t(bfl[nh], cvta_sh(&sBl[krow*BPITCH + ncol]));
                } else {
                    int nrow = wn + nh*16 + (g >> 1)*8 + rr;
                    int kcol = kk + (g & 1)*8;
                    ldsm4(bfh[nh], cvta_sh(&sBh[nrow*40 + kcol]));
                    ldsm4(bfl[nh], cvta_sh(&sBl[nrow*40 + kcol]));
                }
            }
            #pragma unroll
            for (int mi = 0; mi < 2; mi++)
                #pragma unroll
                for (int nh = 0; nh < NH; nh++)
                    #pragma unroll
                    for (int s = 0; s < 2; s++) {
                        int nj = nh*2 + s;
                        mma16816(acc0[mi][nj], afh[mi], &bfh[nh][s*2]);
                        mma16816(acc1[mi][nj], afh[mi], &bfl[nh][s*2]);
                        if (HAS_ALO) mma16816(acc1[mi][nj], afl[mi], &bfh[nh][s*2]);
                    }
        }
        __syncthreads();
    }

    // ---- epilogue (vectorized pairs) ----
    #pragma unroll
    for (int mi = 0; mi < 2; mi++)
        #pragma unroll
        for (int nj = 0; nj < NJ; nj++) {
            int row0 = bm0 + wm + mi*16 + (lane >> 2);
            int col0 = bn0 + wn + nj*8 + ((lane & 3) << 1);
            #pragma unroll
            for (int hh = 0; hh < 2; hh++) {
                int row = row0 + hh*8;
                size_t off = coff + (size_t)row*ldc + col0;
                float v0 = (acc0[mi][nj][hh*2+0] + INV_LOSCALE*acc1[mi][nj][hh*2+0]) * outscale;
                float v1 = (acc0[mi][nj][hh*2+1] + INV_LOSCALE*acc1[mi][nj][hh*2+1]) * outscale;
                if (HAS_RES) {
                    float2 r2 = *(const float2*)(R + off);
                    v0 += r2.x; v1 += r2.y;
                }
                if (SPLIT_OUT) {
                    __half h0 = __float2half_rn(v0), h1 = __float2half_rn(v1);
                    *(__half2*)(Ch + off) = __halves2half2(h0, h1);
                    *(__half2*)(Cl + off) = __halves2half2(
                        __float2half_rn((v0 - __half2float(h0)) * LOSCALE),
                        __float2half_rn((v1 - __half2float(h1)) * LOSCALE));
                } else {
                    *(float2*)(Cf + off) = make_float2(v0, v1);
                }
            }
        }
}

// ---------------- write the 4 spike-rate scalars ----------------
__global__ void finalize_kernel(float* __restrict__ out, long long out_size) {
    if (out_size >= (long long)BTND + 4) {
        out[BTND+0] = (float)((double)g_cnt[0] / 4194304.0);   // r_lif1
        out[BTND+1] = (float)((double)g_cnt[1] / 16777216.0);  // r_attn
        out[BTND+2] = (float)((double)g_cnt[2] / 4194304.0);   // r_lif2
        out[BTND+3] = (float)((double)g_cnt[3] / 16777216.0);  // r_ffn
    }
}

// ---------------- host launcher ----------------
extern "C" void kernel_launch(void* const* d_in, const int* in_sizes, int n_in,
                              void* d_out, int out_size) {
    const float* x  = (const float*)d_in[0];
    const float* g1 = (const float*)d_in[1];
    const float* b1 = (const float*)d_in[2];
    const float* wq = (const float*)d_in[3];
    const float* wk = (const float*)d_in[4];
    const float* wv = (const float*)d_in[5];
    const float* wo = (const float*)d_in[6];
    const float* g2 = (const float*)d_in[7];
    const float* b2 = (const float*)d_in[8];
    const float* w1 = (const float*)d_in[9];
    const float* w2 = (const float*)d_in[10];
    float* out = (float*)d_out;

    __half *s1h, *qkvh, *qkvl, *sah, *aoh, *aol, *s2h, *hsh;
    __half *wqkvh,*wqkvl,*woh,*wol,*w1h,*w1l,*w2h,*w2l;
    float *sc, *xm, *hid;
    unsigned long long* cnt;
    cudaGetSymbolAddress((void**)&s1h,  g_s1h);
    cudaGetSymbolAddress((void**)&qkvh, g_qkvh); cudaGetSymbolAddress((void**)&qkvl, g_qkvl);
    cudaGetSymbolAddress((void**)&sc,   g_scores);
    cudaGetSymbolAddress((void**)&sah,  g_sah);
    cudaGetSymbolAddress((void**)&aoh,  g_aoh);  cudaGetSymbolAddress((void**)&aol,  g_aol);
    cudaGetSymbolAddress((void**)&xm,   g_xm);
    cudaGetSymbolAddress((void**)&s2h,  g_s2h);
    cudaGetSymbolAddress((void**)&hid,  g_hid);
    cudaGetSymbolAddress((void**)&hsh,  g_hsh);
    cudaGetSymbolAddress((void**)&wqkvh,g_wqkvh);cudaGetSymbolAddress((void**)&wqkvl,g_wqkvl);
    cudaGetSymbolAddress((void**)&woh,  g_woh);  cudaGetSymbolAddress((void**)&wol,  g_wol);
    cudaGetSymbolAddress((void**)&w1h,  g_w1h);  cudaGetSymbolAddress((void**)&w1l,  g_w1l);
    cudaGetSymbolAddress((void**)&w2h,  g_w2h);  cudaGetSymbolAddress((void**)&w2l,  g_w2l);
    cudaGetSymbolAddress((void**)&cnt,  g_cnt);

    // dynamic smem bytes: 2 stages * STAGE halves * 2B
    const int SMEM_QKV    = 2*((128*40)   + 2*(32*136)) * 2;   // 55296
    const int SMEM_SCORES = 2*(2*(128*40) + 2*(128*40)) * 2;   // 81920
    const int SMEM_AO     = 2*((128*40)   + 2*(32*72 )) * 2;   // 38912
    const int SMEM_WO     = 2*(2*(128*40) + 2*(32*136)) * 2;   // 75776
    const int SMEM_W12    = SMEM_QKV;

    cudaFuncSetAttribute(mma_gemm<false,true ,true ,false,128>, cudaFuncAttributeMaxDynamicSharedMemorySize, SMEM_QKV);
    cudaFuncSetAttribute(mma_gemm<true ,false,false,false,128>, cudaFuncAttributeMaxDynamicSharedMemorySize, SMEM_SCORES);
    cudaFuncSetAttribute(mma_gemm<false,true ,true ,false,64 >, cudaFuncAttributeMaxDynamicSharedMemorySize, SMEM_AO);
    cudaFuncSetAttribute(mma_gemm<true ,true ,false,true ,128>, cudaFuncAttributeMaxDynamicSharedMemorySize, SMEM_WO);
    cudaFuncSetAttribute(mma_gemm<false,true ,false,false,128>, cudaFuncAttributeMaxDynamicSharedMemorySize, SMEM_W12);
    cudaFuncSetAttribute(mma_gemm<false,true ,false,true ,128>, cudaFuncAttributeMaxDynamicSharedMemorySize, SMEM_W12);

    zero_cnt_kernel<<<1, 32>>>();

    // weight splits
    split_qkv_kernel<<<(3*Dd*Dd)/256, 256>>>(wq, wk, wv, wqkvh, wqkvl);
    split_kernel<<<(Dd*Dd)/256,   256>>>(wo, woh, wol, Dd*Dd);
    split_kernel<<<(Dd*HIDd)/256, 256>>>(w1, w1h, w1l, Dd*HIDd);
    split_kernel<<<(HIDd*Dd)/256, 256>>>(w2, w2h, w2l, HIDd*Dd);

    // ---- attention branch ----
    ln_lif_kernel<<<Bb*Nn, 512>>>(x, g1, b1, s1h, cnt + 0);

    // fused QKV: binary A (s1) @ [wq|wk|wv], split outputs into qkv buffer
    mma_gemm<false,true,true,false,128><<<dim3(QKVW/128, BTN/128), 256, SMEM_QKV>>>(
        s1h, nullptr, wqkvh, wqkvl, nullptr, nullptr, qkvh, qkvl,
        Dd, Dd, QKVW, QKVW, 1, 0,0, 0,0, 0,0, 1.f);

    // scores = 0.125 * q @ k^T (batched over B*T*H), 3-term split
    mma_gemm<true,false,false,false,128><<<dim3(Nn/128, Nn/128, Bb*Tt*Hh), 256, SMEM_SCORES>>>(
        qkvh, qkvl, qkvh + Dd, qkvl + Dd, nullptr, sc, nullptr, nullptr,
        DHh, QKVW, QKVW, Nn,
        Hh, (long long)Nn*QKVW, 64LL, (long long)Nn*QKVW, 64LL,
        (long long)Hh*Nn*Nn, (long long)Nn*Nn, 0.125f);

    lif_time_kernel<<<16384, 256>>>(sc, sah, Hh*Nn*Nn, 0.5f, cnt + 1);

    // attnout = sa @ v (batched), binary A, split B = v slice of qkv
    mma_gemm<false,true,true,false,64><<<dim3(DHh/64, Nn/128, Bb*Tt*Hh), 256, SMEM_AO>>>(
        sah, nullptr, qkvh + 2*Dd, qkvl + 2*Dd, nullptr, nullptr, aoh, aol,
        Nn, Nn, QKVW, Dd,
        Hh, (long long)Hh*Nn*Nn, (long long)Nn*Nn,
        (long long)Nn*QKVW, 64LL, (long long)Nn*Dd, 64LL, 1.f);

    // xm = x + ao @ wo  (3-term)
    mma_gemm<true,true,false,true,128><<<dim3(Dd/128, BTN/128), 256, SMEM_WO>>>(
        aoh, aol, woh, wol, x, xm, nullptr, nullptr,
        Dd, Dd, Dd, Dd, 1, 0,0, 0,0, 0,0, 1.f);

    // ---- MLP branch ----
    ln_lif_kernel<<<Bb*Nn, 512>>>(xm, g2, b2, s2h, cnt + 2);

    // hid = s2 @ w1
    mma_gemm<false,true,false,false,128><<<dim3(HIDd/128, BTN/128), 256, SMEM_W12>>>(
        s2h, nullptr, w1h, w1l, nullptr, hid, nullptr, nullptr,
        Dd, Dd, HIDd, HIDd, 1, 0,0, 0,0, 0,0, 1.f);

    lif_time_kernel<<<16384, 256>>>(hid, hsh, Nn*HIDd, 1.0f, cnt + 3);

    // out = xm + hs @ w2
    mma_gemm<false,true,false,true,128><<<dim3(Dd/128, BTN/128), 256, SMEM_W12>>>(
        hsh, nullptr, w2h, w2l, xm, out, nullptr, nullptr,
        HIDd, HIDd, Dd, Dd, 1, 0,0, 0,0, 0,0, 1.f);

    finalize_kernel<<<1, 1>>>(out, (long long)out_size);
}

// round 7
// speedup vs baseline: 1.0367x; 1.0367x over previous
#include <cuda_runtime.h>
#include <cuda_fp16.h>
#include <cstdint>

// ---------------- problem dims ----------------
#define Bb   8
#define Tt   4
#define Nn   256
#define Dd   512
#define Hh   8
#define DHh  64
#define HIDd 2048
#define BTN  (Bb*Tt*Nn)            // 8192 rows
#define BTND ((size_t)BTN*Dd)      // 4194304
#define SCORES_ELEMS ((size_t)Bb*Tt*Hh*Nn*Nn)  // 16777216
#define HID_ELEMS    ((size_t)BTN*HIDd)        // 16777216
#define QKVW (3*Dd)                // 1536

#define BETA 0.95122942450071403f  // fp32(exp(-1/20))
#define LOSCALE 2048.0f
#define INV_LOSCALE (1.0f/2048.0f)

// ---------------- scratch (static device globals; no allocation) ----------------
__device__ __half g_s1h[BTND];
__device__ __half g_qkvh[(size_t)BTN*QKVW], g_qkvl[(size_t)BTN*QKVW];
__device__ float  g_scores[SCORES_ELEMS];
__device__ __half g_sah[SCORES_ELEMS];
__device__ __half g_aoh[BTND], g_aol[BTND];
__device__ float  g_xm[BTND];
__device__ __half g_s2h[BTND];
__device__ float  g_hid[HID_ELEMS];
__device__ __half g_hsh[HID_ELEMS];
// weight splits
__device__ __half g_wqkvh[Dd*QKVW], g_wqkvl[Dd*QKVW];
__device__ __half g_woh[Dd*Dd], g_wol[Dd*Dd];
__device__ __half g_w1h[Dd*HIDd], g_w1l[Dd*HIDd];
__device__ __half g_w2h[HIDd*Dd], g_w2l[HIDd*Dd];
__device__ unsigned long long g_cnt[4];

// ---------------- counters ----------------
__global__ void zero_cnt_kernel() {
    if (threadIdx.x < 4) g_cnt[threadIdx.x] = 0ULL;
}

// ---------------- all weight splits in one launch ----------------
// segment 0: wq|wk|wv -> wqkv (interleaved columns), 1: wo, 2: w1, 3: w2
__global__ void split_all_kernel(const float* __restrict__ wq,
                                 const float* __restrict__ wk,
                                 const float* __restrict__ wv,
                                 const float* __restrict__ wo,
                                 const float* __restrict__ w1,
                                 const float* __restrict__ w2,
                                 __half* __restrict__ qkvh, __half* __restrict__ qkvl,
                                 __half* __restrict__ woh,  __half* __restrict__ wol,
                                 __half* __restrict__ w1h,  __half* __restrict__ w1l,
                                 __half* __restrict__ w2h,  __half* __restrict__ w2l) {
    int i = blockIdx.x*blockDim.x + threadIdx.x;
    const int QKV_N = 3*Dd*Dd;          // 786432
    const int WO_N  = Dd*Dd;            // 262144
    const int W1_N  = Dd*HIDd;          // 1048576
    const int W2_N  = HIDd*Dd;          // 1048576
    float v; __half* hi; __half* lo; size_t off;
    if (i < QKV_N) {
        int which = i / (Dd*Dd);
        int rem = i % (Dd*Dd);
        int r = rem / Dd, c = rem % Dd;
        const float* src = (which == 0) ? wq : (which == 1) ? wk : wv;
        v = src[rem];
        hi = qkvh; lo = qkvl; off = (size_t)r*QKVW + which*Dd + c;
    } else if (i < QKV_N + WO_N) {
        int j = i - QKV_N;
        v = wo[j]; hi = woh; lo = wol; off = j;
    } else if (i < QKV_N + WO_N + W1_N) {
        int j = i - QKV_N - WO_N;
        v = w1[j]; hi = w1h; lo = w1l; off = j;
    } else if (i < QKV_N + WO_N + W1_N + W2_N) {
        int j = i - QKV_N - WO_N - W1_N;
        v = w2[j]; hi = w2h; lo = w2l; off = j;
    } else return;
    __half h = __float2half_rn(v);
    hi[off] = h;
    lo[off] = __float2half_rn((v - __half2float(h)) * LOSCALE);
}

// ---------------- block reduction (512 threads) ----------------
__device__ __forceinline__ float block_sum(float v, float* red) {
    int lane = threadIdx.x & 31, w = threadIdx.x >> 5;
    #pragma unroll
    for (int off = 16; off; off >>= 1) v += __shfl_down_sync(0xffffffffu, v, off);
    __syncthreads();
    if (lane == 0) red[w] = v;
    __syncthreads();
    if (threadIdx.x < 32) {
        float t = (threadIdx.x < 16) ? red[threadIdx.x] : 0.f;
        #pragma unroll
        for (int off = 8; off; off >>= 1) t += __shfl_down_sync(0xffffffffu, t, off);
        if (threadIdx.x == 0) red[32] = t;
    }
    __syncthreads();
    return red[32];
}

// ---------------- LayerNorm + LIF over time (per (b,n) row) ----------------
__global__ void ln_lif_kernel(const float* __restrict__ x,
                              const float* __restrict__ g,
                              const float* __restrict__ bia,
                              __half* __restrict__ sp,
                              unsigned long long* __restrict__ counter) {
    __shared__ float red[33];
    int bn = blockIdx.x;
    int b  = bn / Nn, n = bn % Nn;
    int d  = threadIdx.x;
    float gg = g[d], bb = bia[d];
    float mem = 0.f;
    float cnt = 0.f;
    for (int t = 0; t < Tt; ++t) {
        size_t rowoff = ((((size_t)b*Tt + t)*Nn) + n)*Dd;
        float v = x[rowoff + d];
        float mean = block_sum(v, red) * (1.f/Dd);
        float diff = v - mean;
        float var = block_sum(diff*diff, red) * (1.f/Dd);
        float h = diff * rsqrtf(var + 1e-5f) * gg + bb;
        mem = BETA*mem + h;
        float s = (mem >= 1.0f) ? 1.f : 0.f;
        mem -= s;
        sp[rowoff + d] = __float2half_rn(s);
        cnt += s;
    }
    float tot = block_sum(cnt, red);
    if (d == 0) atomicAdd(counter, (unsigned long long)(tot + 0.5f));
}

// ---------------- LIF over time axis: fp32 src -> binary fp16 spikes ----------------
__global__ void lif_time_kernel(const float* __restrict__ src, __half* __restrict__ dst,
                                int inner_sz, float thr,
                                unsigned long long* __restrict__ counter) {
    long long total = (long long)Bb * inner_sz;
    long long idx = (long long)blockIdx.x*blockDim.x + threadIdx.x;
    int cnt = 0;
    if (idx < total) {
        long long b = idx / inner_sz, r = idx % inner_sz;
        const float* p = src + (size_t)b*Tt*inner_sz + r;
        __half* q = dst + (size_t)b*Tt*inner_sz + r;
        float mem = 0.f;
        #pragma unroll
        for (int t = 0; t < Tt; ++t) {
            float v2 = p[(size_t)t*inner_sz];
            mem = BETA*mem + v2;
            float s = (mem >= thr) ? 1.f : 0.f;
            q[(size_t)t*inner_sz] = __float2half_rn(s);
            mem -= s*thr;
            cnt += (int)s;
        }
    }
    #pragma unroll
    for (int off = 16; off; off >>= 1) cnt += __shfl_down_sync(0xffffffffu, cnt, off);
    if ((threadIdx.x & 31) == 0 && cnt) atomicAdd(counter, (unsigned long long)cnt);
}

// ---------------- fp16 MMA primitives ----------------
__device__ __forceinline__ uint32_t cvta_sh(const void* p) {
    return (uint32_t)__cvta_generic_to_shared(p);
}
__device__ __forceinline__ void ldsm4(uint32_t* r, uint32_t addr) {
    asm volatile("ldmatrix.sync.aligned.m8n8.x4.shared.b16 {%0,%1,%2,%3}, [%4];\n"
        : "=r"(r[0]), "=r"(r[1]), "=r"(r[2]), "=r"(r[3]) : "r"(addr));
}
__device__ __forceinline__ void ldsm4t(uint32_t* r, uint32_t addr) {
    asm volatile("ldmatrix.sync.aligned.m8n8.x4.trans.shared.b16 {%0,%1,%2,%3}, [%4];\n"
        : "=r"(r[0]), "=r"(r[1]), "=r"(r[2]), "=r"(r[3]) : "r"(addr));
}
__device__ __forceinline__ void mma16816(float* c, const uint32_t* a, const uint32_t* b) {
    asm volatile("mma.sync.aligned.m16n8k16.row.col.f32.f16.f16.f32 "
        "{%0,%1,%2,%3},{%4,%5,%6,%7},{%8,%9},{%0,%1,%2,%3};\n"
        : "+f"(c[0]), "+f"(c[1]), "+f"(c[2]), "+f"(c[3])
        : "r"(a[0]), "r"(a[1]), "r"(a[2]), "r"(a[3]), "r"(b[0]), "r"(b[1]));
}
__device__ __forceinline__ void cp16(void* smem, const void* gmem) {
    asm volatile("cp.async.cg.shared.global [%0], [%1], 16;\n"
        :: "r"(cvta_sh(smem)), "l"(gmem));
}
#define CP_COMMIT() asm volatile("cp.async.commit_group;\n")
template<int N>
__device__ __forceinline__ void cp_wait() {
    asm volatile("cp.async.wait_group %0;\n" :: "n"(N));
}

// ---------------- generic split-fp16 MMA GEMM, NS-stage cp.async pipeline ----------------
// C = (Ahi@Bhi + 2^-11*(Ahi@Blo [+ Alo@Bhi])) * outscale [+ R]
// Block tile 128 x TN (TN=128 or 64), BK=32, 256 threads (8 warps, 4x2 warp grid).
// BT=true : B is k-major [K x N] row-major (standard GEMM), ldmatrix.trans
// BT=false: B is n-major [N x K] row-major (C = A@B^T), ldmatrix
// Pipeline: each iteration issues the load for stage (it+NS-1) (or an empty commit
// to keep the group cadence uniform), then cp.async.wait_group NS-1 completes the
// oldest group (stage it).
template<bool HAS_ALO, bool BT, bool SPLIT_OUT, bool HAS_RES, int TN, int NS>
__global__ void __launch_bounds__(256, 1)
mma_gemm(const __half* __restrict__ Ah, const __half* __restrict__ Al,
         const __half* __restrict__ Bh, const __half* __restrict__ Bl,
         const float* __restrict__ R, float* __restrict__ Cf,
         __half* __restrict__ Ch, __half* __restrict__ Cl,
         int K, int lda, int ldb, int ldc,
         int zdiv,
         long long sA1, long long sA2,
         long long sB1, long long sB2,
         long long sC1, long long sC2,
         float outscale)
{
    extern __shared__ __half sm[];
    constexpr int AH_SZ  = 128*40;                          // 5120 halves
    constexpr int A_SZ   = HAS_ALO ? 2*AH_SZ : AH_SZ;
    constexpr int BPITCH = BT ? (TN + 8) : 40;
    constexpr int B_SZ   = BT ? 32*BPITCH : TN*40;          // per hi/lo tile
    constexpr int STAGE  = A_SZ + 2*B_SZ;
    constexpr int WN     = TN/2;                            // per-warp N width
    constexpr int NH     = WN/16;                           // 16-col ldsm groups
    constexpr int NJ     = 2*NH;                            // 8-col mma tiles
    constexpr int BCHUNK_ITERS = (32*TN/8)/256;             // 2 (TN=128) or 1 (TN=64)

    int tid = threadIdx.x, lane = tid & 31, wid = tid >> 5;
    int wm = (wid & 3) * 32, wn = (wid >> 2) * WN;
    int bm0 = blockIdx.y * 128, bn0 = blockIdx.x * TN;
    int z = blockIdx.z, z1 = z / zdiv, z2 = z % zdiv;
    size_t aoff = (size_t)z1*sA1 + (size_t)z2*sA2;
    size_t boff = (size_t)z1*sB1 + (size_t)z2*sB2;
    size_t coff = (size_t)z1*sC1 + (size_t)z2*sC2;

    float acc0[2][NJ][4] = {};
    float acc1[2][NJ][4] = {};

    auto load_stage = [&](int k0, int st) {
        __half* base = sm + st*STAGE;
        #pragma unroll
        for (int i = 0; i < 2; i++) {                    // 512 A chunks of 8 halves
            int idx = tid + i*256;
            int row = idx >> 2, col = (idx & 3) << 3;
            cp16(&base[row*40 + col],
                 Ah + aoff + (size_t)(bm0+row)*lda + k0 + col);
            if (HAS_ALO)
                cp16(&base[AH_SZ + row*40 + col],
                     Al + aoff + (size_t)(bm0+row)*lda + k0 + col);
        }
        __half* sBh = base + A_SZ;
        __half* sBl = sBh + B_SZ;
        #pragma unroll
        for (int i = 0; i < BCHUNK_ITERS; i++) {
            int idx = tid + i*256;
            if (BT) {
                int row = idx / (TN/8), col = (idx % (TN/8)) << 3;   // 32 x TN
                cp16(&sBh[row*BPITCH + col], Bh + boff + (size_t)(k0+row)*ldb + bn0 + col);
                cp16(&sBl[row*BPITCH + col], Bl + boff + (size_t)(k0+row)*ldb + bn0 + col);
            } else {
                int row = idx >> 2, col = (idx & 3) << 3;            // TN x 32
                cp16(&sBh[row*40 + col], Bh + boff + (size_t)(bn0+row)*ldb + k0 + col);
                cp16(&sBl[row*40 + col], Bl + boff + (size_t)(bn0+row)*ldb + k0 + col);
            }
        }
        CP_COMMIT();
    };

    // prologue: stages 0..NS-2 (uniform commit cadence)
    #pragma unroll
    for (int s = 0; s < NS-1; s++) {
        if (s*32 < K) load_stage(s*32, s);
        else CP_COMMIT();
    }

    int it = 0;
    for (int k0 = 0; k0 < K; k0 += 32, ++it) {
        // issue the load that keeps NS groups in flight
        int kpre = k0 + (NS-1)*32;
        if (kpre < K) load_stage(kpre, (it + NS-1) % NS);
        else CP_COMMIT();

        cp_wait<NS-1>();
        __syncthreads();

        __half* base = sm + (it % NS)*STAGE;
        __half* sAh = base;
        __half* sAl = base + AH_SZ;
        __half* sBh = base + A_SZ;
        __half* sBl = sBh + B_SZ;

        #pragma unroll
        for (int kk = 0; kk < 32; kk += 16) {
            uint32_t afh[2][4], afl[2][4];
            #pragma unroll
            for (int mi = 0; mi < 2; mi++) {
                int row = wm + mi*16 + (lane & 15);
                int col = kk + ((lane >> 4) << 3);
                ldsm4(afh[mi], cvta_sh(&sAh[row*40 + col]));
                if (HAS_ALO) ldsm4(afl[mi], cvta_sh(&sAl[row*40 + col]));
            }
            uint32_t bfh[NH][4], bfl[NH][4];
            int g = lane >> 3, rr = lane & 7;
            #pragma unroll
            for (int nh = 0; nh < NH; nh++) {
                if (BT) {
                    int krow = kk + (g & 1)*8 + rr;
                    int ncol = wn + nh*16 + (g >> 1)*8;
                    ldsm4t(bfh[nh], cvta_sh(&sBh[krow*BPITCH + ncol]));
                    ldsm4t(bfl[nh], cvta_sh(&sBl[krow*BPITCH + ncol]));
                } else {
                    int nrow = wn + nh*16 + (g >> 1)*8 + rr;
                    int kcol = kk + (g & 1)*8;
                    ldsm4(bfh[nh], cvta_sh(&sBh[nrow*40 + kcol]));
                    ldsm4(bfl[nh], cvta_sh(&sBl[nrow*40 + kcol]));
                }
            }
            #pragma unroll
            for (int mi = 0; mi < 2; mi++)
                #pragma unroll
                for (int nh = 0; nh < NH; nh++)
                    #pragma unroll
                    for (int s = 0; s < 2; s++) {
                        int nj = nh*2 + s;
                        mma16816(acc0[mi][nj], afh[mi], &bfh[nh][s*2]);
                        mma16816(acc1[mi][nj], afh[mi], &bfl[nh][s*2]);
                        if (HAS_ALO) mma16816(acc1[mi][nj], afl[mi], &bfh[nh][s*2]);
                    }
        }
        __syncthreads();
    }

    // ---- epilogue (vectorized pairs) ----
    #pragma unroll
    for (int mi = 0; mi < 2; mi++)
        #pragma unroll
        for (int nj = 0; nj < NJ; nj++) {
            int row0 = bm0 + wm + mi*16 + (lane >> 2);
            int col0 = bn0 + wn + nj*8 + ((lane & 3) << 1);
            #pragma unroll
            for (int hh = 0; hh < 2; hh++) {
                int row = row0 + hh*8;
                size_t off = coff + (size_t)row*ldc + col0;
                float v0 = (acc0[mi][nj][hh*2+0] + INV_LOSCALE*acc1[mi][nj][hh*2+0]) * outscale;
                float v1 = (acc0[mi][nj][hh*2+1] + INV_LOSCALE*acc1[mi][nj][hh*2+1]) * outscale;
                if (HAS_RES) {
                    float2 r2 = *(const float2*)(R + off);
                    v0 += r2.x; v1 += r2.y;
                }
                if (SPLIT_OUT) {
                    __half h0 = __float2half_rn(v0), h1 = __float2half_rn(v1);
                    *(__half2*)(Ch + off) = __halves2half2(h0, h1);
                    *(__half2*)(Cl + off) = __halves2half2(
                        __float2half_rn((v0 - __half2float(h0)) * LOSCALE),
                        __float2half_rn((v1 - __half2float(h1)) * LOSCALE));
                } else {
                    *(float2*)(Cf + off) = make_float2(v0, v1);
                }
            }
        }
}

// ---------------- write the 4 spike-rate scalars ----------------
__global__ void finalize_kernel(float* __restrict__ out, long long out_size) {
    if (out_size >= (long long)BTND + 4) {
        out[BTND+0] = (float)((double)g_cnt[0] / 4194304.0);   // r_lif1
        out[BTND+1] = (float)((double)g_cnt[1] / 16777216.0);  // r_attn
        out[BTND+2] = (float)((double)g_cnt[2] / 4194304.0);   // r_lif2
        out[BTND+3] = (float)((double)g_cnt[3] / 16777216.0);  // r_ffn
    }
}

// ---------------- host launcher ----------------
extern "C" void kernel_launch(void* const* d_in, const int* in_sizes, int n_in,
                              void* d_out, int out_size) {
    const float* x  = (const float*)d_in[0];
    const float* g1 = (const float*)d_in[1];
    const float* b1 = (const float*)d_in[2];
    const float* wq = (const float*)d_in[3];
    const float* wk = (const float*)d_in[4];
    const float* wv = (const float*)d_in[5];
    const float* wo = (const float*)d_in[6];
    const float* g2 = (const float*)d_in[7];
    const float* b2 = (const float*)d_in[8];
    const float* w1 = (const float*)d_in[9];
    const float* w2 = (const float*)d_in[10];
    float* out = (float*)d_out;

    __half *s1h, *qkvh, *qkvl, *sah, *aoh, *aol, *s2h, *hsh;
    __half *wqkvh,*wqkvl,*woh,*wol,*w1h,*w1l,*w2h,*w2l;
    float *sc, *xm, *hid;
    unsigned long long* cnt;
    cudaGetSymbolAddress((void**)&s1h,  g_s1h);
    cudaGetSymbolAddress((void**)&qkvh, g_qkvh); cudaGetSymbolAddress((void**)&qkvl, g_qkvl);
    cudaGetSymbolAddress((void**)&sc,   g_scores);
    cudaGetSymbolAddress((void**)&sah,  g_sah);
    cudaGetSymbolAddress((void**)&aoh,  g_aoh);  cudaGetSymbolAddress((void**)&aol,  g_aol);
    cudaGetSymbolAddress((void**)&xm,   g_xm);
    cudaGetSymbolAddress((void**)&s2h,  g_s2h);
    cudaGetSymbolAddress((void**)&hid,  g_hid);
    cudaGetSymbolAddress((void**)&hsh,  g_hsh);
    cudaGetSymbolAddress((void**)&wqkvh,g_wqkvh);cudaGetSymbolAddress((void**)&wqkvl,g_wqkvl);
    cudaGetSymbolAddress((void**)&woh,  g_woh);  cudaGetSymbolAddress((void**)&wol,  g_wol);
    cudaGetSymbolAddress((void**)&w1h,  g_w1h);  cudaGetSymbolAddress((void**)&w1l,  g_w1l);
    cudaGetSymbolAddress((void**)&w2h,  g_w2h);  cudaGetSymbolAddress((void**)&w2l,  g_w2l);
    cudaGetSymbolAddress((void**)&cnt,  g_cnt);

    // dynamic smem bytes: NS stages * STAGE halves * 2B
    const int SMEM_QKV    = 3*((128*40)   + 2*(32*136)) * 2;   // 82944  (NS=3)
    const int SMEM_SCORES = 1*(2*(128*40) + 2*(128*40)) * 2;   // 40960  (NS=1)
    const int SMEM_AO     = 3*((128*40)   + 2*(32*72 )) * 2;   // 58368  (NS=3)
    const int SMEM_WO     = 3*(2*(128*40) + 2*(32*136)) * 2;   // 113664 (NS=3)
    const int SMEM_W12    = SMEM_QKV;

    cudaFuncSetAttribute(mma_gemm<false,true ,true ,false,128,3>, cudaFuncAttributeMaxDynamicSharedMemorySize, SMEM_QKV);
    cudaFuncSetAttribute(mma_gemm<true ,false,false,false,128,1>, cudaFuncAttributeMaxDynamicSharedMemorySize, SMEM_SCORES);
    cudaFuncSetAttribute(mma_gemm<false,true ,true ,false,64 ,3>, cudaFuncAttributeMaxDynamicSharedMemorySize, SMEM_AO);
    cudaFuncSetAttribute(mma_gemm<true ,true ,false,true ,128,3>, cudaFuncAttributeMaxDynamicSharedMemorySize, SMEM_WO);
    cudaFuncSetAttribute(mma_gemm<false,true ,false,false,128,3>, cudaFuncAttributeMaxDynamicSharedMemorySize, SMEM_W12);
    cudaFuncSetAttribute(mma_gemm<false,true ,false,true ,128,3>, cudaFuncAttributeMaxDynamicSharedMemorySize, SMEM_W12);

    zero_cnt_kernel<<<1, 32>>>();

    // all weight splits in one launch (3.1M elems)
    split_all_kernel<<<(3*Dd*Dd + Dd*Dd + 2*Dd*HIDd + 255)/256, 256>>>(
        wq, wk, wv, wo, w1, w2,
        wqkvh, wqkvl, woh, wol, w1h, w1l, w2h, w2l);

    // ---- attention branch ----
    ln_lif_kernel<<<Bb*Nn, 512>>>(x, g1, b1, s1h, cnt + 0);

    // fused QKV: binary A (s1) @ [wq|wk|wv], split outputs into qkv buffer
    mma_gemm<false,true,true,false,128,3><<<dim3(QKVW/128, BTN/128), 256, SMEM_QKV>>>(
        s1h, nullptr, wqkvh, wqkvl, nullptr, nullptr, qkvh, qkvl,
        Dd, Dd, QKVW, QKVW, 1, 0,0, 0,0, 0,0, 1.f);

    // scores = 0.125 * q @ k^T (batched over B*T*H), 3-term split, NS=1 (K=64, occ-driven)
    mma_gemm<true,false,false,false,128,1><<<dim3(Nn/128, Nn/128, Bb*Tt*Hh), 256, SMEM_SCORES>>>(
        qkvh, qkvl, qkvh + Dd, qkvl + Dd, nullptr, sc, nullptr, nullptr,
        DHh, QKVW, QKVW, Nn,
        Hh, (long long)Nn*QKVW, 64LL, (long long)Nn*QKVW, 64LL,
        (long long)Hh*Nn*Nn, (long long)Nn*Nn, 0.125f);

    lif_time_kernel<<<16384, 256>>>(sc, sah, Hh*Nn*Nn, 0.5f, cnt + 1);

    // attnout = sa @ v (batched), binary A, split B = v slice of qkv
    mma_gemm<false,true,true,false,64,3><<<dim3(DHh/64, Nn/128, Bb*Tt*Hh), 256, SMEM_AO>>>(
        sah, nullptr, qkvh + 2*Dd, qkvl + 2*Dd, nullptr, nullptr, aoh, aol,
        Nn, Nn, QKVW, Dd,
        Hh, (long long)Hh*Nn*Nn, (long long)Nn*Nn,
        (long long)Nn*QKVW, 64LL, (long long)Nn*Dd, 64LL, 1.f);

    // xm = x + ao @ wo  (3-term)
    mma_gemm<true,true,false,true,128,3><<<dim3(Dd/128, BTN/128), 256, SMEM_WO>>>(
        aoh, aol, woh, wol, x, xm, nullptr, nullptr,
        Dd, Dd, Dd, Dd, 1, 0,0, 0,0, 0,0, 1.f);

    // ---- MLP branch ----
    ln_lif_kernel<<<Bb*Nn, 512>>>(xm, g2, b2, s2h, cnt + 2);

    // hid = s2 @ w1
    mma_gemm<false,true,false,false,128,3><<<dim3(HIDd/128, BTN/128), 256, SMEM_W12>>>(
        s2h, nullptr, w1h, w1l, nullptr, hid, nullptr, nullptr,
        Dd, Dd, HIDd, HIDd, 1, 0,0, 0,0, 0,0, 1.f);

    lif_time_kernel<<<16384, 256>>>(hid, hsh, Nn*HIDd, 1.0f, cnt + 3);

    // out = xm + hs @ w2
    mma_gemm<false,true,false,true,128,3><<<dim3(Dd/128, BTN/128), 256, SMEM_W12>>>(
        hsh, nullptr, w2h, w2l, xm, out, nullptr, nullptr,
        HIDd, HIDd, Dd, Dd, 1, 0,0, 0,0, 0,0, 1.f);

    finalize_kernel<<<1, 1>>>(out, (long long)out_size);
}

// round 11
// speedup vs baseline: 1.2286x; 1.1851x over previous
#include <cuda_runtime.h>
#include <cuda_fp16.h>
#include <cstdint>

// ---------------- problem dims ----------------
#define Bb   8
#define Tt   4
#define Nn   256
#define Dd   512
#define Hh   8
#define DHh  64
#define HIDd 2048
#define BTN  (Bb*Tt*Nn)            // 8192 rows
#define BTND ((size_t)BTN*Dd)      // 4194304
#define SCORES_ELEMS ((size_t)Bb*Tt*Hh*Nn*Nn)  // 16777216
#define HID_ELEMS    ((size_t)BTN*HIDd)        // 16777216
#define QKVW (3*Dd)                // 1536

#define BETA 0.95122942450071403f  // fp32(exp(-1/20))

// ---------------- scratch (static device globals; no allocation) ----------------
__device__ __half g_s1h[BTND];
__device__ __half g_qkvh[(size_t)BTN*QKVW], g_qkvl[(size_t)BTN*QKVW];
__device__ float  g_scores[SCORES_ELEMS];
__device__ __half g_sah[SCORES_ELEMS];
__device__ __half g_aoh[BTND], g_aol[BTND];
__device__ float  g_xm[BTND];
__device__ __half g_s2h[BTND];
__device__ float  g_hid[HID_ELEMS];
__device__ __half g_hsh[HID_ELEMS];
// weight splits (residual lo stored UNSCALED)
__device__ __half g_wqkvh[Dd*QKVW], g_wqkvl[Dd*QKVW];
__device__ __half g_woh[Dd*Dd], g_wol[Dd*Dd];
__device__ __half g_w1h[Dd*HIDd], g_w1l[Dd*HIDd];
__device__ __half g_w2h[HIDd*Dd], g_w2l[HIDd*Dd];
__device__ unsigned long long g_cnt[4];

// ---------------- counters ----------------
__global__ void zero_cnt_kernel() {
    if (threadIdx.x < 4) g_cnt[threadIdx.x] = 0ULL;
}

// ---------------- all weight splits in one launch ----------------
__global__ void split_all_kernel(const float* __restrict__ wq,
                                 const float* __restrict__ wk,
                                 const float* __restrict__ wv,
                                 const float* __restrict__ wo,
                                 const float* __restrict__ w1,
                                 const float* __restrict__ w2,
                                 __half* __restrict__ qkvh, __half* __restrict__ qkvl,
                                 __half* __restrict__ woh,  __half* __restrict__ wol,
                                 __half* __restrict__ w1h,  __half* __restrict__ w1l,
                                 __half* __restrict__ w2h,  __half* __restrict__ w2l) {
    int i = blockIdx.x*blockDim.x + threadIdx.x;
    const int QKV_N = 3*Dd*Dd;
    const int WO_N  = Dd*Dd;
    const int W1_N  = Dd*HIDd;
    const int W2_N  = HIDd*Dd;
    float v; __half* hi; __half* lo; size_t off;
    if (i < QKV_N) {
        int which = i / (Dd*Dd);
        int rem = i % (Dd*Dd);
        int r = rem / Dd, c = rem % Dd;
        const float* src = (which == 0) ? wq : (which == 1) ? wk : wv;
        v = src[rem];
        hi = qkvh; lo = qkvl; off = (size_t)r*QKVW + which*Dd + c;
    } else if (i < QKV_N + WO_N) {
        int j = i - QKV_N;
        v = wo[j]; hi = woh; lo = wol; off = j;
    } else if (i < QKV_N + WO_N + W1_N) {
        int j = i - QKV_N - WO_N;
        v = w1[j]; hi = w1h; lo = w1l; off = j;
    } else if (i < QKV_N + WO_N + W1_N + W2_N) {
        int j = i - QKV_N - WO_N - W1_N;
        v = w2[j]; hi = w2h; lo = w2l; off = j;
    } else return;
    __half h = __float2half_rn(v);
    hi[off] = h;
    lo[off] = __float2half_rn(v - __half2float(h));   // unscaled residual
}

// ---------------- block reduction (512 threads) ----------------
__device__ __forceinline__ float block_sum(float v, float* red) {
    int lane = threadIdx.x & 31, w = threadIdx.x >> 5;
    #pragma unroll
    for (int off = 16; off; off >>= 1) v += __shfl_down_sync(0xffffffffu, v, off);
    __syncthreads();
    if (lane == 0) red[w] = v;
    __syncthreads();
    if (threadIdx.x < 32) {
        float t = (threadIdx.x < 16) ? red[threadIdx.x] : 0.f;
        #pragma unroll
        for (int off = 8; off; off >>= 1) t += __shfl_down_sync(0xffffffffu, t, off);
        if (threadIdx.x == 0) red[32] = t;
    }
    __syncthreads();
    return red[32];
}

// ---------------- LayerNorm + LIF over time (per (b,n) row) ----------------
__global__ void ln_lif_kernel(const float* __restrict__ x,
                              const float* __restrict__ g,
                              const float* __restrict__ bia,
                              __half* __restrict__ sp,
                              unsigned long long* __restrict__ counter) {
    __shared__ float red[33];
    int bn = blockIdx.x;
    int b  = bn / Nn, n = bn % Nn;
    int d  = threadIdx.x;
    float gg = g[d], bb = bia[d];
    float mem = 0.f;
    float cnt = 0.f;
    for (int t = 0; t < Tt; ++t) {
        size_t rowoff = ((((size_t)b*Tt + t)*Nn) + n)*Dd;
        float v = x[rowoff + d];
        float mean = block_sum(v, red) * (1.f/Dd);
        float diff = v - mean;
        float var = block_sum(diff*diff, red) * (1.f/Dd);
        float h = diff * rsqrtf(var + 1e-5f) * gg + bb;
        mem = BETA*mem + h;
        float s = (mem >= 1.0f) ? 1.f : 0.f;
        mem -= s;
        sp[rowoff + d] = __float2half_rn(s);
        cnt += s;
    }
    float tot = block_sum(cnt, red);
    if (d == 0) atomicAdd(counter, (unsigned long long)(tot + 0.5f));
}

// ---------------- LIF over time axis: fp32 src -> binary fp16 spikes ----------------
__global__ void lif_time_kernel(const float* __restrict__ src, __half* __restrict__ dst,
                                int inner_sz, float thr,
                                unsigned long long* __restrict__ counter) {
    long long total = (long long)Bb * inner_sz;
    long long idx = (long long)blockIdx.x*blockDim.x + threadIdx.x;
    int cnt = 0;
    if (idx < total) {
        long long b = idx / inner_sz, r = idx % inner_sz;
        const float* p = src + (size_t)b*Tt*inner_sz + r;
        __half* q = dst + (size_t)b*Tt*inner_sz + r;
        float mem = 0.f;
        #pragma unroll
        for (int t = 0; t < Tt; ++t) {
            float v2 = p[(size_t)t*inner_sz];
            mem = BETA*mem + v2;
            float s = (mem >= thr) ? 1.f : 0.f;
            q[(size_t)t*inner_sz] = __float2half_rn(s);
            mem -= s*thr;
            cnt += (int)s;
        }
    }
    #pragma unroll
    for (int off = 16; off; off >>= 1) cnt += __shfl_down_sync(0xffffffffu, cnt, off);
    if ((threadIdx.x & 31) == 0 && cnt) atomicAdd(counter, (unsigned long long)cnt);
}

// ---------------- fp16 MMA primitives ----------------
__device__ __forceinline__ uint32_t cvta_sh(const void* p) {
    return (uint32_t)__cvta_generic_to_shared(p);
}
__device__ __forceinline__ void ldsm4(uint32_t* r, uint32_t addr) {
    asm volatile("ldmatrix.sync.aligned.m8n8.x4.shared.b16 {%0,%1,%2,%3}, [%4];\n"
        : "=r"(r[0]), "=r"(r[1]), "=r"(r[2]), "=r"(r[3]) : "r"(addr));
}
__device__ __forceinline__ void ldsm4t(uint32_t* r, uint32_t addr) {
    asm volatile("ldmatrix.sync.aligned.m8n8.x4.trans.shared.b16 {%0,%1,%2,%3}, [%4];\n"
        : "=r"(r[0]), "=r"(r[1]), "=r"(r[2]), "=r"(r[3]) : "r"(addr));
}
__device__ __forceinline__ void mma16816(float* c, const uint32_t* a, const uint32_t* b) {
    asm volatile("mma.sync.aligned.m16n8k16.row.col.f32.f16.f16.f32 "
        "{%0,%1,%2,%3},{%4,%5,%6,%7},{%8,%9},{%0,%1,%2,%3};\n"
        : "+f"(c[0]), "+f"(c[1]), "+f"(c[2]), "+f"(c[3])
        : "r"(a[0]), "r"(a[1]), "r"(a[2]), "r"(a[3]), "r"(b[0]), "r"(b[1]));
}
__device__ __forceinline__ void cp16(void* smem, const void* gmem) {
    asm volatile("cp.async.cg.shared.global [%0], [%1], 16;\n"
        :: "r"(cvta_sh(smem)), "l"(gmem));
}
#define CP_COMMIT() asm volatile("cp.async.commit_group;\n")
template<int N>
__device__ __forceinline__ void cp_wait() {
    asm volatile("cp.async.wait_group %0;\n" :: "n"(N));
}

// ---------------- split-fp16 MMA GEMM, single fp32 accumulator ----------------
// C = (Ahi@Bhi + Ahi@Blo [+ Alo@Bhi]) * outscale [+ R]   (lo operands are raw residuals)
// Block tile 128 x TN (TN=128 or 64), BK=32, 256 threads (8 warps, 4x2 warp grid).
// BT=true : B is k-major [K x N] row-major (standard GEMM), ldmatrix.trans
// BT=false: B is n-major [N x K] row-major (C = A@B^T), ldmatrix
template<bool HAS_ALO, bool BT, bool SPLIT_OUT, bool HAS_RES, int TN, int NS>
__global__ void __launch_bounds__(256, 2)
mma_gemm(const __half* __restrict__ Ah, const __half* __restrict__ Al,
         const __half* __restrict__ Bh, const __half* __restrict__ Bl,
         const float* __restrict__ R, float* __restrict__ Cf,
         __half* __restrict__ Ch, __half* __restrict__ Cl,
         int K, int lda, int ldb, int ldc,
         int zdiv,
         long long sA1, long long sA2,
         long long sB1, long long sB2,
         long long sC1, long long sC2,
         float outscale)
{
    extern __shared__ __half sm[];
    constexpr int AH_SZ  = 128*40;                          // 5120 halves
    constexpr int A_SZ   = HAS_ALO ? 2*AH_SZ : AH_SZ;
    constexpr int BPITCH = BT ? (TN + 8) : 40;
    constexpr int B_SZ   = BT ? 32*BPITCH : TN*40;          // per hi/lo tile
    constexpr int STAGE  = A_SZ + 2*B_SZ;
    constexpr int WN     = TN/2;                            // per-warp N width
    constexpr int NH     = WN/16;                           // 16-col ldsm groups
    constexpr int NJ     = 2*NH;                            // 8-col mma tiles
    constexpr int BCHUNK_ITERS = (32*TN/8)/256;             // 2 (TN=128) or 1 (TN=64)

    int tid = threadIdx.x, lane = tid & 31, wid = tid >> 5;
    int wm = (wid & 3) * 32, wn = (wid >> 2) * WN;
    int bm0 = blockIdx.y * 128, bn0 = blockIdx.x * TN;
    int z = blockIdx.z, z1 = z / zdiv, z2 = z % zdiv;
    size_t aoff = (size_t)z1*sA1 + (size_t)z2*sA2;
    size_t boff = (size_t)z1*sB1 + (size_t)z2*sB2;
    size_t coff = (size_t)z1*sC1 + (size_t)z2*sC2;

    float acc[2][NJ][4] = {};

    auto load_stage = [&](int k0, int st) {
        __half* base = sm + st*STAGE;
        #pragma unroll
        for (int i = 0; i < 2; i++) {                    // 512 A chunks of 8 halves
            int idx = tid + i*256;
            int row = idx >> 2, col = (idx & 3) << 3;
            cp16(&base[row*40 + col],
                 Ah + aoff + (size_t)(bm0+row)*lda + k0 + col);
            if (HAS_ALO)
                cp16(&base[AH_SZ + row*40 + col],
                     Al + aoff + (size_t)(bm0+row)*lda + k0 + col);
        }
        __half* sBh = base + A_SZ;
        __half* sBl = sBh + B_SZ;
        #pragma unroll
        for (int i = 0; i < BCHUNK_ITERS; i++) {
            int idx = tid + i*256;
            if (BT) {
                int row = idx / (TN/8), col = (idx % (TN/8)) << 3;   // 32 x TN
                cp16(&sBh[row*BPITCH + col], Bh + boff + (size_t)(k0+row)*ldb + bn0 + col);
                cp16(&sBl[row*BPITCH + col], Bl + boff + (size_t)(k0+row)*ldb + bn0 + col);
            } else {
                int row = idx >> 2, col = (idx & 3) << 3;            // TN x 32
                cp16(&sBh[row*40 + col], Bh + boff + (size_t)(bn0+row)*ldb + k0 + col);
                cp16(&sBl[row*40 + col], Bl + boff + (size_t)(bn0+row)*ldb + k0 + col);
            }
        }
        CP_COMMIT();
    };

    // prologue (uniform commit cadence)
    #pragma unroll
    for (int s = 0; s < NS-1; s++) {
        if (s*32 < K) load_stage(s*32, s);
        else CP_COMMIT();
    }

    int it = 0;
    for (int k0 = 0; k0 < K; k0 += 32, ++it) {
        int kpre = k0 + (NS-1)*32;
        if (kpre < K) load_stage(kpre, (it + NS-1) % NS);
        else CP_COMMIT();

        cp_wait<NS-1>();
        __syncthreads();

        __half* base = sm + (it % NS)*STAGE;
        __half* sAh = base;
        __half* sAl = base + AH_SZ;
        __half* sBh = base + A_SZ;
        __half* sBl = sBh + B_SZ;

        #pragma unroll
        for (int kk = 0; kk < 32; kk += 16) {
            uint32_t afh[2][4], afl[2][4];
            #pragma unroll
            for (int mi = 0; mi < 2; mi++) {
                int row = wm + mi*16 + (lane & 15);
                int col = kk + ((lane >> 4) << 3);
                ldsm4(afh[mi], cvta_sh(&sAh[row*40 + col]));
                if (HAS_ALO) ldsm4(afl[mi], cvta_sh(&sAl[row*40 + col]));
            }
            uint32_t bfh[NH][4], bfl[NH][4];
            int g = lane >> 3, rr = lane & 7;
            #pragma unroll
            for (int nh = 0; nh < NH; nh++) {
                if (BT) {
                    int krow = kk + (g & 1)*8 + rr;
                    int ncol = wn + nh*16 + (g >> 1)*8;
                    ldsm4t(bfh[nh], cvta_sh(&sBh[krow*BPITCH + ncol]));
                    ldsm4t(bfl[nh], cvta_sh(&sBl[krow*BPITCH + ncol]));
                } else {
                    int nrow = wn + nh*16 + (g >> 1)*8 + rr;
                    int kcol = kk + (g & 1)*8;
                    ldsm4(bfh[nh], cvta_sh(&sBh[nrow*40 + kcol]));
                    ldsm4(bfl[nh], cvta_sh(&sBl[nrow*40 + kcol]));
                }
            }
            #pragma unroll
            for (int mi = 0; mi < 2; mi++)
                #pragma unroll
                for (int nh = 0; nh < NH; nh++)
                    #pragma unroll
                    for (int s = 0; s < 2; s++) {
                        int nj = nh*2 + s;
                        mma16816(acc[mi][nj], afh[mi], &bfh[nh][s*2]);
                        mma16816(acc[mi][nj], afh[mi], &bfl[nh][s*2]);
                        if (HAS_ALO) mma16816(acc[mi][nj], afl[mi], &bfh[nh][s*2]);
                    }
        }
        __syncthreads();
    }

    // ---- epilogue (vectorized pairs) ----
    #pragma unroll
    for (int mi = 0; mi < 2; mi++)
        #pragma unroll
        for (int nj = 0; nj < NJ; nj++) {
            int row0 = bm0 + wm + mi*16 + (lane >> 2);
            int col0 = bn0 + wn + nj*8 + ((lane & 3) << 1);
            #pragma unroll
            for (int hh = 0; hh < 2; hh++) {
                int row = row0 + hh*8;
                size_t off = coff + (size_t)row*ldc + col0;
                float v0 = acc[mi][nj][hh*2+0] * outscale;
                float v1 = acc[mi][nj][hh*2+1] * outscale;
                if (HAS_RES) {
                    float2 r2 = *(const float2*)(R + off);
                    v0 += r2.x; v1 += r2.y;
                }
                if (SPLIT_OUT) {
                    __half h0 = __float2half_rn(v0), h1 = __float2half_rn(v1);
                    *(__half2*)(Ch + off) = __halves2half2(h0, h1);
                    *(__half2*)(Cl + off) = __halves2half2(
                        __float2half_rn(v0 - __half2float(h0)),
                        __float2half_rn(v1 - __half2float(h1)));
                } else {
                    *(float2*)(Cf + off) = make_float2(v0, v1);
                }
            }
        }
}

// ---------------- write the 4 spike-rate scalars ----------------
__global__ void finalize_kernel(float* __restrict__ out, long long out_size) {
    if (out_size >= (long long)BTND + 4) {
        out[BTND+0] = (float)((double)g_cnt[0] / 4194304.0);   // r_lif1
        out[BTND+1] = (float)((double)g_cnt[1] / 16777216.0);  // r_attn
        out[BTND+2] = (float)((double)g_cnt[2] / 4194304.0);   // r_lif2
        out[BTND+3] = (float)((double)g_cnt[3] / 16777216.0);  // r_ffn
    }
}

// ---------------- host launcher ----------------
extern "C" void kernel_launch(void* const* d_in, const int* in_sizes, int n_in,
                              void* d_out, int out_size) {
    const float* x  = (const float*)d_in[0];
    const float* g1 = (const float*)d_in[1];
    const float* b1 = (const float*)d_in[2];
    const float* wq = (const float*)d_in[3];
    const float* wk = (const float*)d_in[4];
    const float* wv = (const float*)d_in[5];
    const float* wo = (const float*)d_in[6];
    const float* g2 = (const float*)d_in[7];
    const float* b2 = (const float*)d_in[8];
    const float* w1 = (const float*)d_in[9];
    const float* w2 = (const float*)d_in[10];
    float* out = (float*)d_out;

    __half *s1h, *qkvh, *qkvl, *sah, *aoh, *aol, *s2h, *hsh;
    __half *wqkvh,*wqkvl,*woh,*wol,*w1h,*w1l,*w2h,*w2l;
    float *sc, *xm, *hid;
    unsigned long long* cnt;
    cudaGetSymbolAddress((void**)&s1h,  g_s1h);
    cudaGetSymbolAddress((void**)&qkvh, g_qkvh); cudaGetSymbolAddress((void**)&qkvl, g_qkvl);
    cudaGetSymbolAddress((void**)&sc,   g_scores);
    cudaGetSymbolAddress((void**)&sah,  g_sah);
    cudaGetSymbolAddress((void**)&aoh,  g_aoh);  cudaGetSymbolAddress((void**)&aol,  g_aol);
    cudaGetSymbolAddress((void**)&xm,   g_xm);
    cudaGetSymbolAddress((void**)&s2h,  g_s2h);
    cudaGetSymbolAddress((void**)&hid,  g_hid);
    cudaGetSymbolAddress((void**)&hsh,  g_hsh);
    cudaGetSymbolAddress((void**)&wqkvh,g_wqkvh);cudaGetSymbolAddress((void**)&wqkvl,g_wqkvl);
    cudaGetSymbolAddress((void**)&woh,  g_woh);  cudaGetSymbolAddress((void**)&wol,  g_wol);
    cudaGetSymbolAddress((void**)&w1h,  g_w1h);  cudaGetSymbolAddress((void**)&w1l,  g_w1l);
    cudaGetSymbolAddress((void**)&w2h,  g_w2h);  cudaGetSymbolAddress((void**)&w2l,  g_w2l);
    cudaGetSymbolAddress((void**)&cnt,  g_cnt);

    // dynamic smem bytes: NS stages * STAGE halves * 2B
    const int SMEM_QKV    = 3*((128*40)   + 2*(32*136)) * 2;   // 82944  (NS=3)
    const int SMEM_SCORES = 1*(2*(128*40) + 2*(128*40)) * 2;   // 40960  (NS=1)
    const int SMEM_AO     = 3*((128*40)   + 2*(32*72 )) * 2;   // 58368  (NS=3)
    const int SMEM_WO     = 2*(2*(128*40) + 2*(32*136)) * 2;   // 75776  (NS=2)
    const int SMEM_W12    = SMEM_QKV;

    cudaFuncSetAttribute(mma_gemm<false,true ,true ,false,128,3>, cudaFuncAttributeMaxDynamicSharedMemorySize, SMEM_QKV);
    cudaFuncSetAttribute(mma_gemm<true ,false,false,false,128,1>, cudaFuncAttributeMaxDynamicSharedMemorySize, SMEM_SCORES);
    cudaFuncSetAttribute(mma_gemm<false,true ,true ,false,64 ,3>, cudaFuncAttributeMaxDynamicSharedMemorySize, SMEM_AO);
    cudaFuncSetAttribute(mma_gemm<true ,true ,false,true ,128,2>, cudaFuncAttributeMaxDynamicSharedMemorySize, SMEM_WO);
    cudaFuncSetAttribute(mma_gemm<false,true ,false,false,128,3>, cudaFuncAttributeMaxDynamicSharedMemorySize, SMEM_W12);
    cudaFuncSetAttribute(mma_gemm<false,true ,false,true ,128,3>, cudaFuncAttributeMaxDynamicSharedMemorySize, SMEM_W12);

    zero_cnt_kernel<<<1, 32>>>();

    // all weight splits in one launch
    split_all_kernel<<<(3*Dd*Dd + Dd*Dd + 2*Dd*HIDd + 255)/256, 256>>>(
        wq, wk, wv, wo, w1, w2,
        wqkvh, wqkvl, woh, wol, w1h, w1l, w2h, w2l);

    // ---- attention branch ----
    ln_lif_kernel<<<Bb*Nn, 512>>>(x, g1, b1, s1h, cnt + 0);

    // fused QKV: binary A (s1) @ [wq|wk|wv], split outputs into qkv buffer
    mma_gemm<false,true,true,false,128,3><<<dim3(QKVW/128, BTN/128), 256, SMEM_QKV>>>(
        s1h, nullptr, wqkvh, wqkvl, nullptr, nullptr, qkvh, qkvl,
        Dd, Dd, QKVW, QKVW, 1, 0,0, 0,0, 0,0, 1.f);

    // scores = 0.125 * q @ k^T (batched over B*T*H), 3-term, NS=1
    mma_gemm<true,false,false,false,128,1><<<dim3(Nn/128, Nn/128, Bb*Tt*Hh), 256, SMEM_SCORES>>>(
        qkvh, qkvl, qkvh + Dd, qkvl + Dd, nullptr, sc, nullptr, nullptr,
        DHh, QKVW, QKVW, Nn,
        Hh, (long long)Nn*QKVW, 64LL, (long long)Nn*QKVW, 64LL,
        (long long)Hh*Nn*Nn, (long long)Nn*Nn, 0.125f);

    lif_time_kernel<<<16384, 256>>>(sc, sah, Hh*Nn*Nn, 0.5f, cnt + 1);

    // attnout = sa @ v (batched), binary A, split B = v slice of qkv
    mma_gemm<false,true,true,false,64,3><<<dim3(DHh/64, Nn/128, Bb*Tt*Hh), 256, SMEM_AO>>>(
        sah, nullptr, qkvh + 2*Dd, qkvl + 2*Dd, nullptr, nullptr, aoh, aol,
        Nn, Nn, QKVW, Dd,
        Hh, (long long)Hh*Nn*Nn, (long long)Nn*Nn,
        (long long)Nn*QKVW, 64LL, (long long)Nn*Dd, 64LL, 1.f);

    // xm = x + ao @ wo  (3-term)
    mma_gemm<true,true,false,true,128,2><<<dim3(Dd/128, BTN/128), 256, SMEM_WO>>>(
        aoh, aol, woh, wol, x, xm, nullptr, nullptr,
        Dd, Dd, Dd, Dd, 1, 0,0, 0,0, 0,0, 1.f);

    // ---- MLP branch ----
    ln_lif_kernel<<<Bb*Nn, 512>>>(xm, g2, b2, s2h, cnt + 2);

    // hid = s2 @ w1
    mma_gemm<false,true,false,false,128,3><<<dim3(HIDd/128, BTN/128), 256, SMEM_W12>>>(
        s2h, nullptr, w1h, w1l, nullptr, hid, nullptr, nullptr,
        Dd, Dd, HIDd, HIDd, 1, 0,0, 0,0, 0,0, 1.f);

    lif_time_kernel<<<16384, 256>>>(hid, hsh, Nn*HIDd, 1.0f, cnt + 3);

    // out = xm + hs @ w2
    mma_gemm<false,true,false,true,128,3><<<dim3(Dd/128, BTN/128), 256, SMEM_W12>>>(
        hsh, nullptr, w2h, w2l, xm, out, nullptr, nullptr,
        HIDd, HIDd, Dd, Dd, 1, 0,0, 0,0, 0,0, 1.f);

    finalize_kernel<<<1, 1>>>(out, (long long)out_size);
}

// round 12
// speedup vs baseline: 1.2542x; 1.0208x over previous
#include <cuda_runtime.h>
#include <cuda_fp16.h>
#include <cstdint>

// ---------------- problem dims ----------------
#define Bb   8
#define Tt   4
#define Nn   256
#define Dd   512
#define Hh   8
#define DHh  64
#define HIDd 2048
#define BTN  (Bb*Tt*Nn)            // 8192 rows
#define BTND ((size_t)BTN*Dd)      // 4194304
#define SCORES_ELEMS ((size_t)Bb*Tt*Hh*Nn*Nn)  // 16777216
#define HID_ELEMS    ((size_t)BTN*HIDd)        // 16777216
#define QKVW (3*Dd)                // 1536

#define BETA 0.95122942450071403f  // fp32(exp(-1/20))

// ---------------- scratch (static device globals; no allocation) ----------------
__device__ __half g_s1h[BTND];
__device__ __half g_qkvh[(size_t)BTN*QKVW], g_qkvl[(size_t)BTN*QKVW];
__device__ float  g_scores[SCORES_ELEMS];
__device__ __half g_sah[SCORES_ELEMS];
__device__ __half g_aoh[BTND], g_aol[BTND];
__device__ float  g_xm[BTND];
__device__ __half g_s2h[BTND];
__device__ float  g_hid[HID_ELEMS];
__device__ __half g_hsh[HID_ELEMS];
// weight splits (residual lo stored UNSCALED)
__device__ __half g_wqkvh[Dd*QKVW], g_wqkvl[Dd*QKVW];
__device__ __half g_woh[Dd*Dd], g_wol[Dd*Dd];
__device__ __half g_w1h[Dd*HIDd], g_w1l[Dd*HIDd];
__device__ __half g_w2h[HIDd*Dd], g_w2l[HIDd*Dd];
__device__ unsigned long long g_cnt[4];

// ---------------- counters ----------------
__global__ void zero_cnt_kernel() {
    if (threadIdx.x < 4) g_cnt[threadIdx.x] = 0ULL;
}

// ---------------- all weight splits in one launch ----------------
__global__ void split_all_kernel(const float* __restrict__ wq,
                                 const float* __restrict__ wk,
                                 const float* __restrict__ wv,
                                 const float* __restrict__ wo,
                                 const float* __restrict__ w1,
                                 const float* __restrict__ w2,
                                 __half* __restrict__ qkvh, __half* __restrict__ qkvl,
                                 __half* __restrict__ woh,  __half* __restrict__ wol,
                                 __half* __restrict__ w1h,  __half* __restrict__ w1l,
                                 __half* __restrict__ w2h,  __half* __restrict__ w2l) {
    int i = blockIdx.x*blockDim.x + threadIdx.x;
    const int QKV_N = 3*Dd*Dd;
    const int WO_N  = Dd*Dd;
    const int W1_N  = Dd*HIDd;
    const int W2_N  = HIDd*Dd;
    float v; __half* hi; __half* lo; size_t off;
    if (i < QKV_N) {
        int which = i / (Dd*Dd);
        int rem = i % (Dd*Dd);
        int r = rem / Dd, c = rem % Dd;
        const float* src = (which == 0) ? wq : (which == 1) ? wk : wv;
        v = src[rem];
        hi = qkvh; lo = qkvl; off = (size_t)r*QKVW + which*Dd + c;
    } else if (i < QKV_N + WO_N) {
        int j = i - QKV_N;
        v = wo[j]; hi = woh; lo = wol; off = j;
    } else if (i < QKV_N + WO_N + W1_N) {
        int j = i - QKV_N - WO_N;
        v = w1[j]; hi = w1h; lo = w1l; off = j;
    } else if (i < QKV_N + WO_N + W1_N + W2_N) {
        int j = i - QKV_N - WO_N - W1_N;
        v = w2[j]; hi = w2h; lo = w2l; off = j;
    } else return;
    __half h = __float2half_rn(v);
    hi[off] = h;
    lo[off] = __float2half_rn(v - __half2float(h));   // unscaled residual
}

// ---------------- block reduction (512 threads) ----------------
__device__ __forceinline__ float block_sum(float v, float* red) {
    int lane = threadIdx.x & 31, w = threadIdx.x >> 5;
    #pragma unroll
    for (int off = 16; off; off >>= 1) v += __shfl_down_sync(0xffffffffu, v, off);
    __syncthreads();
    if (lane == 0) red[w] = v;
    __syncthreads();
    if (threadIdx.x < 32) {
        float t = (threadIdx.x < 16) ? red[threadIdx.x] : 0.f;
        #pragma unroll
        for (int off = 8; off; off >>= 1) t += __shfl_down_sync(0xffffffffu, t, off);
        if (threadIdx.x == 0) red[32] = t;
    }
    __syncthreads();
    return red[32];
}

// ---------------- LayerNorm + LIF over time (per (b,n) row) ----------------
__global__ void ln_lif_kernel(const float* __restrict__ x,
                              const float* __restrict__ g,
                              const float* __restrict__ bia,
                              __half* __restrict__ sp,
                              unsigned long long* __restrict__ counter) {
    __shared__ float red[33];
    int bn = blockIdx.x;
    int b  = bn / Nn, n = bn % Nn;
    int d  = threadIdx.x;
    float gg = g[d], bb = bia[d];
    float mem = 0.f;
    float cnt = 0.f;
    for (int t = 0; t < Tt; ++t) {
        size_t rowoff = ((((size_t)b*Tt + t)*Nn) + n)*Dd;
        float v = x[rowoff + d];
        float mean = block_sum(v, red) * (1.f/Dd);
        float diff = v - mean;
        float var = block_sum(diff*diff, red) * (1.f/Dd);
        float h = diff * rsqrtf(var + 1e-5f) * gg + bb;
        mem = BETA*mem + h;
        float s = (mem >= 1.0f) ? 1.f : 0.f;
        mem -= s;
        sp[rowoff + d] = __float2half_rn(s);
        cnt += s;
    }
    float tot = block_sum(cnt, red);
    if (d == 0) atomicAdd(counter, (unsigned long long)(tot + 0.5f));
}

// ---------------- LIF over time axis: fp32 src -> binary fp16 spikes ----------------
__global__ void lif_time_kernel(const float* __restrict__ src, __half* __restrict__ dst,
                                int inner_sz, float thr,
                                unsigned long long* __restrict__ counter) {
    long long total = (long long)Bb * inner_sz;
    long long idx = (long long)blockIdx.x*blockDim.x + threadIdx.x;
    int cnt = 0;
    if (idx < total) {
        long long b = idx / inner_sz, r = idx % inner_sz;
        const float* p = src + (size_t)b*Tt*inner_sz + r;
        __half* q = dst + (size_t)b*Tt*inner_sz + r;
        float mem = 0.f;
        #pragma unroll
        for (int t = 0; t < Tt; ++t) {
            float v2 = p[(size_t)t*inner_sz];
            mem = BETA*mem + v2;
            float s = (mem >= thr) ? 1.f : 0.f;
            q[(size_t)t*inner_sz] = __float2half_rn(s);
            mem -= s*thr;
            cnt += (int)s;
        }
    }
    #pragma unroll
    for (int off = 16; off; off >>= 1) cnt += __shfl_down_sync(0xffffffffu, cnt, off);
    if ((threadIdx.x & 31) == 0 && cnt) atomicAdd(counter, (unsigned long long)cnt);
}

// ---------------- fp16 MMA primitives ----------------
__device__ __forceinline__ uint32_t cvta_sh(const void* p) {
    return (uint32_t)__cvta_generic_to_shared(p);
}
__device__ __forceinline__ void ldsm4(uint32_t* r, uint32_t addr) {
    asm volatile("ldmatrix.sync.aligned.m8n8.x4.shared.b16 {%0,%1,%2,%3}, [%4];\n"
        : "=r"(r[0]), "=r"(r[1]), "=r"(r[2]), "=r"(r[3]) : "r"(addr));
}
__device__ __forceinline__ void ldsm4t(uint32_t* r, uint32_t addr) {
    asm volatile("ldmatrix.sync.aligned.m8n8.x4.trans.shared.b16 {%0,%1,%2,%3}, [%4];\n"
        : "=r"(r[0]), "=r"(r[1]), "=r"(r[2]), "=r"(r[3]) : "r"(addr));
}
__device__ __forceinline__ void mma16816(float* c, const uint32_t* a, const uint32_t* b) {
    asm volatile("mma.sync.aligned.m16n8k16.row.col.f32.f16.f16.f32 "
        "{%0,%1,%2,%3},{%4,%5,%6,%7},{%8,%9},{%0,%1,%2,%3};\n"
        : "+f"(c[0]), "+f"(c[1]), "+f"(c[2]), "+f"(c[3])
        : "r"(a[0]), "r"(a[1]), "r"(a[2]), "r"(a[3]), "r"(b[0]), "r"(b[1]));
}
__device__ __forceinline__ void cp16(void* smem, const void* gmem) {
    asm volatile("cp.async.cg.shared.global [%0], [%1], 16;\n"
        :: "r"(cvta_sh(smem)), "l"(gmem));
}
#define CP_COMMIT() asm volatile("cp.async.commit_group;\n")
template<int N>
__device__ __forceinline__ void cp_wait() {
    asm volatile("cp.async.wait_group %0;\n" :: "n"(N));
}

// ---------------- split-fp16 MMA GEMM, single fp32 accumulator ----------------
// C = (Ahi@Bhi + Ahi@Blo [+ Alo@Bhi]) * outscale [+ R]   (lo operands are raw residuals)
// Block tile 128 x TN (TN=128 or 64), BK=32, 256 threads.
// Warp grid 2x4: warp tile 64(M) x TN/4(N) -- minimizes smem crossbar traffic
// (A fragments shared 4x across warp columns, B shared 2x across warp rows).
// BT=true : B is k-major [K x N] row-major (standard GEMM), ldmatrix.trans
// BT=false: B is n-major [N x K] row-major (C = A@B^T), ldmatrix
template<bool HAS_ALO, bool BT, bool SPLIT_OUT, bool HAS_RES, int TN, int NS>
__global__ void __launch_bounds__(256, 2)
mma_gemm(const __half* __restrict__ Ah, const __half* __restrict__ Al,
         const __half* __restrict__ Bh, const __half* __restrict__ Bl,
         const float* __restrict__ R, float* __restrict__ Cf,
         __half* __restrict__ Ch, __half* __restrict__ Cl,
         int K, int lda, int ldb, int ldc,
         int zdiv,
         long long sA1, long long sA2,
         long long sB1, long long sB2,
         long long sC1, long long sC2,
         float outscale)
{
    extern __shared__ __half sm[];
    constexpr int AH_SZ  = 128*40;                          // 5120 halves
    constexpr int A_SZ   = HAS_ALO ? 2*AH_SZ : AH_SZ;
    constexpr int BPITCH = BT ? (TN + 8) : 40;
    constexpr int B_SZ   = BT ? 32*BPITCH : TN*40;          // per hi/lo tile
    constexpr int STAGE  = A_SZ + 2*B_SZ;
    constexpr int WN     = TN/4;                            // per-warp N width (32 or 16)
    constexpr int NH     = WN/16;                           // 16-col ldsm groups (2 or 1)
    constexpr int NJ     = 2*NH;                            // 8-col mma tiles
    constexpr int MI     = 4;                               // 64 M rows per warp / 16
    constexpr int BCHUNK_ITERS = (32*TN/8)/256;             // 2 (TN=128) or 1 (TN=64)

    int tid = threadIdx.x, lane = tid & 31, wid = tid >> 5;
    int wm = (wid >> 2) * 64, wn = (wid & 3) * WN;
    int bm0 = blockIdx.y * 128, bn0 = blockIdx.x * TN;
    int z = blockIdx.z, z1 = z / zdiv, z2 = z % zdiv;
    size_t aoff = (size_t)z1*sA1 + (size_t)z2*sA2;
    size_t boff = (size_t)z1*sB1 + (size_t)z2*sB2;
    size_t coff = (size_t)z1*sC1 + (size_t)z2*sC2;

    float acc[MI][NJ][4] = {};

    auto load_stage = [&](int k0, int st) {
        __half* base = sm + st*STAGE;
        #pragma unroll
        for (int i = 0; i < 2; i++) {                    // 512 A chunks of 8 halves
            int idx = tid + i*256;
            int row = idx >> 2, col = (idx & 3) << 3;
            cp16(&base[row*40 + col],
                 Ah + aoff + (size_t)(bm0+row)*lda + k0 + col);
            if (HAS_ALO)
                cp16(&base[AH_SZ + row*40 + col],
                     Al + aoff + (size_t)(bm0+row)*lda + k0 + col);
        }
        __half* sBh = base + A_SZ;
        __half* sBl = sBh + B_SZ;
        #pragma unroll
        for (int i = 0; i < BCHUNK_ITERS; i++) {
            int idx = tid + i*256;
            if (BT) {
                int row = idx / (TN/8), col = (idx % (TN/8)) << 3;   // 32 x TN
                cp16(&sBh[row*BPITCH + col], Bh + boff + (size_t)(k0+row)*ldb + bn0 + col);
                cp16(&sBl[row*BPITCH + col], Bl + boff + (size_t)(k0+row)*ldb + bn0 + col);
            } else {
                int row = idx >> 2, col = (idx & 3) << 3;            // TN x 32
                cp16(&sBh[row*40 + col], Bh + boff + (size_t)(bn0+row)*ldb + k0 + col);
                cp16(&sBl[row*40 + col], Bl + boff + (size_t)(bn0+row)*ldb + k0 + col);
            }
        }
        CP_COMMIT();
    };

    // prologue (uniform commit cadence)
    #pragma unroll
    for (int s = 0; s < NS-1; s++) {
        if (s*32 < K) load_stage(s*32, s);
        else CP_COMMIT();
    }

    int it = 0;
    for (int k0 = 0; k0 < K; k0 += 32, ++it) {
        int kpre = k0 + (NS-1)*32;
        if (kpre < K) load_stage(kpre, (it + NS-1) % NS);
        else CP_COMMIT();

        cp_wait<NS-1>();
        __syncthreads();

        __half* base = sm + (it % NS)*STAGE;
        __half* sAh = base;
        __half* sAl = base + AH_SZ;
        __half* sBh = base + A_SZ;
        __half* sBl = sBh + B_SZ;

        #pragma unroll
        for (int kk = 0; kk < 32; kk += 16) {
            uint32_t afh[MI][4], afl[MI][4];
            #pragma unroll
            for (int mi = 0; mi < MI; mi++) {
                int row = wm + mi*16 + (lane & 15);
                int col = kk + ((lane >> 4) << 3);
                ldsm4(afh[mi], cvta_sh(&sAh[row*40 + col]));
                if (HAS_ALO) ldsm4(afl[mi], cvta_sh(&sAl[row*40 + col]));
            }
            uint32_t bfh[NH][4], bfl[NH][4];
            int g = lane >> 3, rr = lane & 7;
            #pragma unroll
            for (int nh = 0; nh < NH; nh++) {
                if (BT) {
                    int krow = kk + (g & 1)*8 + rr;
                    int ncol = wn + nh*16 + (g >> 1)*8;
                    ldsm4t(bfh[nh], cvta_sh(&sBh[krow*BPITCH + ncol]));
                    ldsm4t(bfl[nh], cvta_sh(&sBl[krow*BPITCH + ncol]));
                } else {
                    int nrow = wn + nh*16 + (g >> 1)*8 + rr;
                    int kcol = kk + (g & 1)*8;
                    ldsm4(bfh[nh], cvta_sh(&sBh[nrow*40 + kcol]));
                    ldsm4(bfl[nh], cvta_sh(&sBl[nrow*40 + kcol]));
                }
            }
            #pragma unroll
            for (int mi = 0; mi < MI; mi++)
                #pragma unroll
                for (int nh = 0; nh < NH; nh++)
                    #pragma unroll
                    for (int s = 0; s < 2; s++) {
                        int nj = nh*2 + s;
                        mma16816(acc[mi][nj], afh[mi], &bfh[nh][s*2]);
                        mma16816(acc[mi][nj], afh[mi], &bfl[nh][s*2]);
                        if (HAS_ALO) mma16816(acc[mi][nj], afl[mi], &bfh[nh][s*2]);
                    }
        }
        __syncthreads();
    }

    // ---- epilogue (vectorized pairs) ----
    #pragma unroll
    for (int mi = 0; mi < MI; mi++)
        #pragma unroll
        for (int nj = 0; nj < NJ; nj++) {
            int row0 = bm0 + wm + mi*16 + (lane >> 2);
            int col0 = bn0 + wn + nj*8 + ((lane & 3) << 1);
            #pragma unroll
            for (int hh = 0; hh < 2; hh++) {
                int row = row0 + hh*8;
                size_t off = coff + (size_t)row*ldc + col0;
                float v0 = acc[mi][nj][hh*2+0] * outscale;
                float v1 = acc[mi][nj][hh*2+1] * outscale;
                if (HAS_RES) {
                    float2 r2 = *(const float2*)(R + off);
                    v0 += r2.x; v1 += r2.y;
                }
                if (SPLIT_OUT) {
                    __half h0 = __float2half_rn(v0), h1 = __float2half_rn(v1);
                    *(__half2*)(Ch + off) = __halves2half2(h0, h1);
                    *(__half2*)(Cl + off) = __halves2half2(
                        __float2half_rn(v0 - __half2float(h0)),
                        __float2half_rn(v1 - __half2float(h1)));
                } else {
                    *(float2*)(Cf + off) = make_float2(v0, v1);
                }
            }
        }
}

// ---------------- write the 4 spike-rate scalars ----------------
__global__ void finalize_kernel(float* __restrict__ out, long long out_size) {
    if (out_size >= (long long)BTND + 4) {
        out[BTND+0] = (float)((double)g_cnt[0] / 4194304.0);   // r_lif1
        out[BTND+1] = (float)((double)g_cnt[1] / 16777216.0);  // r_attn
        out[BTND+2] = (float)((double)g_cnt[2] / 4194304.0);   // r_lif2
        out[BTND+3] = (float)((double)g_cnt[3] / 16777216.0);  // r_ffn
    }
}

// ---------------- host launcher ----------------
extern "C" void kernel_launch(void* const* d_in, const int* in_sizes, int n_in,
                              void* d_out, int out_size) {
    const float* x  = (const float*)d_in[0];
    const float* g1 = (const float*)d_in[1];
    const float* b1 = (const float*)d_in[2];
    const float* wq = (const float*)d_in[3];
    const float* wk = (const float*)d_in[4];
    const float* wv = (const float*)d_in[5];
    const float* wo = (const float*)d_in[6];
    const float* g2 = (const float*)d_in[7];
    const float* b2 = (const float*)d_in[8];
    const float* w1 = (const float*)d_in[9];
    const float* w2 = (const float*)d_in[10];
    float* out = (float*)d_out;

    __half *s1h, *qkvh, *qkvl, *sah, *aoh, *aol, *s2h, *hsh;
    __half *wqkvh,*wqkvl,*woh,*wol,*w1h,*w1l,*w2h,*w2l;
    float *sc, *xm, *hid;
    unsigned long long* cnt;
    cudaGetSymbolAddress((void**)&s1h,  g_s1h);
    cudaGetSymbolAddress((void**)&qkvh, g_qkvh); cudaGetSymbolAddress((void**)&qkvl, g_qkvl);
    cudaGetSymbolAddress((void**)&sc,   g_scores);
    cudaGetSymbolAddress((void**)&sah,  g_sah);
    cudaGetSymbolAddress((void**)&aoh,  g_aoh);  cudaGetSymbolAddress((void**)&aol,  g_aol);
    cudaGetSymbolAddress((void**)&xm,   g_xm);
    cudaGetSymbolAddress((void**)&s2h,  g_s2h);
    cudaGetSymbolAddress((void**)&hid,  g_hid);
    cudaGetSymbolAddress((void**)&hsh,  g_hsh);
    cudaGetSymbolAddress((void**)&wqkvh,g_wqkvh);cudaGetSymbolAddress((void**)&wqkvl,g_wqkvl);
    cudaGetSymbolAddress((void**)&woh,  g_woh);  cudaGetSymbolAddress((void**)&wol,  g_wol);
    cudaGetSymbolAddress((void**)&w1h,  g_w1h);  cudaGetSymbolAddress((void**)&w1l,  g_w1l);
    cudaGetSymbolAddress((void**)&w2h,  g_w2h);  cudaGetSymbolAddress((void**)&w2l,  g_w2l);
    cudaGetSymbolAddress((void**)&cnt,  g_cnt);

    // dynamic smem bytes: NS stages * STAGE halves * 2B
    const int SMEM_QKV    = 3*((128*40)   + 2*(32*136)) * 2;   // 82944  (NS=3)
    const int SMEM_SCORES = 1*(2*(128*40) + 2*(128*40)) * 2;   // 40960  (NS=1)
    const int SMEM_AO     = 3*((128*40)   + 2*(32*72 )) * 2;   // 58368  (NS=3)
    const int SMEM_WO     = 2*(2*(128*40) + 2*(32*136)) * 2;   // 75776  (NS=2)
    const int SMEM_W12    = SMEM_QKV;

    cudaFuncSetAttribute(mma_gemm<false,true ,true ,false,128,3>, cudaFuncAttributeMaxDynamicSharedMemorySize, SMEM_QKV);
    cudaFuncSetAttribute(mma_gemm<true ,false,false,false,128,1>, cudaFuncAttributeMaxDynamicSharedMemorySize, SMEM_SCORES);
    cudaFuncSetAttribute(mma_gemm<false,true ,true ,false,64 ,3>, cudaFuncAttributeMaxDynamicSharedMemorySize, SMEM_AO);
    cudaFuncSetAttribute(mma_gemm<true ,true ,false,true ,128,2>, cudaFuncAttributeMaxDynamicSharedMemorySize, SMEM_WO);
    cudaFuncSetAttribute(mma_gemm<false,true ,false,false,128,3>, cudaFuncAttributeMaxDynamicSharedMemorySize, SMEM_W12);
    cudaFuncSetAttribute(mma_gemm<false,true ,false,true ,128,3>, cudaFuncAttributeMaxDynamicSharedMemorySize, SMEM_W12);

    zero_cnt_kernel<<<1, 32>>>();

    // all weight splits in one launch
    split_all_kernel<<<(3*Dd*Dd + Dd*Dd + 2*Dd*HIDd + 255)/256, 256>>>(
        wq, wk, wv, wo, w1, w2,
        wqkvh, wqkvl, woh, wol, w1h, w1l, w2h, w2l);

    // ---- attention branch ----
    ln_lif_kernel<<<Bb*Nn, 512>>>(x, g1, b1, s1h, cnt + 0);

    // fused QKV: binary A (s1) @ [wq|wk|wv], split outputs into qkv buffer
    mma_gemm<false,true,true,false,128,3><<<dim3(QKVW/128, BTN/128), 256, SMEM_QKV>>>(
        s1h, nullptr, wqkvh, wqkvl, nullptr, nullptr, qkvh, qkvl,
        Dd, Dd, QKVW, QKVW, 1, 0,0, 0,0, 0,0, 1.f);

    // scores = 0.125 * q @ k^T (batched over B*T*H), 3-term, NS=1
    mma_gemm<true,false,false,false,128,1><<<dim3(Nn/128, Nn/128, Bb*Tt*Hh), 256, SMEM_SCORES>>>(
        qkvh, qkvl, qkvh + Dd, qkvl + Dd, nullptr, sc, nullptr, nullptr,
        DHh, QKVW, QKVW, Nn,
        Hh, (long long)Nn*QKVW, 64LL, (long long)Nn*QKVW, 64LL,
        (long long)Hh*Nn*Nn, (long long)Nn*Nn, 0.125f);

    lif_time_kernel<<<16384, 256>>>(sc, sah, Hh*Nn*Nn, 0.5f, cnt + 1);

    // attnout = sa @ v (batched), binary A, split B = v slice of qkv
    mma_gemm<false,true,true,false,64,3><<<dim3(DHh/64, Nn/128, Bb*Tt*Hh), 256, SMEM_AO>>>(
        sah, nullptr, qkvh + 2*Dd, qkvl + 2*Dd, nullptr, nullptr, aoh, aol,
        Nn, Nn, QKVW, Dd,
        Hh, (long long)Hh*Nn*Nn, (long long)Nn*Nn,
        (long long)Nn*QKVW, 64LL, (long long)Nn*Dd, 64LL, 1.f);

    // xm = x + ao @ wo  (3-term)
    mma_gemm<true,true,false,true,128,2><<<dim3(Dd/128, BTN/128), 256, SMEM_WO>>>(
        aoh, aol, woh, wol, x, xm, nullptr, nullptr,
        Dd, Dd, Dd, Dd, 1, 0,0, 0,0, 0,0, 1.f);

    // ---- MLP branch ----
    ln_lif_kernel<<<Bb*Nn, 512>>>(xm, g2, b2, s2h, cnt + 2);

    // hid = s2 @ w1
    mma_gemm<false,true,false,false,128,3><<<dim3(HIDd/128, BTN/128), 256, SMEM_W12>>>(
        s2h, nullptr, w1h, w1l, nullptr, hid, nullptr, nullptr,
        Dd, Dd, HIDd, HIDd, 1, 0,0, 0,0, 0,0, 1.f);

    lif_time_kernel<<<16384, 256>>>(hid, hsh, Nn*HIDd, 1.0f, cnt + 3);

    // out = xm + hs @ w2
    mma_gemm<false,true,false,true,128,3><<<dim3(Dd/128, BTN/128), 256, SMEM_W12>>>(
        hsh, nullptr, w2h, w2l, xm, out, nullptr, nullptr,
        HIDd, HIDd, Dd, Dd, 1, 0,0, 0,0, 0,0, 1.f);

    finalize_kernel<<<1, 1>>>(out, (long long)out_size);
}

// round 13
// speedup vs baseline: 1.4234x; 1.1349x over previous
#include <cuda_runtime.h>
#include <cuda_fp16.h>
#include <cstdint>

// ---------------- problem dims ----------------
#define Bb   8
#define Tt   4
#define Nn   256
#define Dd   512
#define Hh   8
#define DHh  64
#define HIDd 2048
#define BTN  (Bb*Tt*Nn)            // 8192 rows
#define BTND ((size_t)BTN*Dd)      // 4194304
#define SCORES_ELEMS ((size_t)Bb*Tt*Hh*Nn*Nn)  // 16777216
#define HID_ELEMS    ((size_t)BTN*HIDd)        // 16777216
#define QKVW (3*Dd)                // 1536

#define BETA 0.95122942450071403f  // fp32(exp(-1/20))

// ---------------- scratch (static device globals; no allocation) ----------------
__device__ __half g_s1h[BTND];
__device__ __half g_qkvh[(size_t)BTN*QKVW], g_qkvl[(size_t)BTN*QKVW];
__device__ float  g_scores[SCORES_ELEMS];
__device__ __half g_sah[SCORES_ELEMS];
__device__ __half g_aoh[BTND], g_aol[BTND];
__device__ float  g_xm[BTND];
__device__ __half g_s2h[BTND];
__device__ float  g_hid[HID_ELEMS];
__device__ __half g_hsh[HID_ELEMS];
// weight splits (residual lo stored UNSCALED)
__device__ __half g_wqkvh[Dd*QKVW], g_wqkvl[Dd*QKVW];
__device__ __half g_woh[Dd*Dd], g_wol[Dd*Dd];
__device__ __half g_w1h[Dd*HIDd], g_w1l[Dd*HIDd];
__device__ __half g_w2h[HIDd*Dd];                 // w2 lo dropped (last layer, no LIF after)
__device__ unsigned long long g_cnt[4];

// ---------------- counters ----------------
__global__ void zero_cnt_kernel() {
    if (threadIdx.x < 4) g_cnt[threadIdx.x] = 0ULL;
}

// ---------------- all weight splits in one launch ----------------
__global__ void split_all_kernel(const float* __restrict__ wq,
                                 const float* __restrict__ wk,
                                 const float* __restrict__ wv,
                                 const float* __restrict__ wo,
                                 const float* __restrict__ w1,
                                 const float* __restrict__ w2,
                                 __half* __restrict__ qkvh, __half* __restrict__ qkvl,
                                 __half* __restrict__ woh,  __half* __restrict__ wol,
                                 __half* __restrict__ w1h,  __half* __restrict__ w1l,
                                 __half* __restrict__ w2h) {
    int i = blockIdx.x*blockDim.x + threadIdx.x;
    const int QKV_N = 3*Dd*Dd;
    const int WO_N  = Dd*Dd;
    const int W1_N  = Dd*HIDd;
    const int W2_N  = HIDd*Dd;
    if (i < QKV_N) {
        int which = i / (Dd*Dd);
        int rem = i % (Dd*Dd);
        int r = rem / Dd, c = rem % Dd;
        const float* src = (which == 0) ? wq : (which == 1) ? wk : wv;
        float v = src[rem];
        __half h = __float2half_rn(v);
        size_t off = (size_t)r*QKVW + which*Dd + c;
        qkvh[off] = h;
        qkvl[off] = __float2half_rn(v - __half2float(h));
    } else if (i < QKV_N + WO_N) {
        int j = i - QKV_N;
        float v = wo[j];
        __half h = __float2half_rn(v);
        woh[j] = h;
        wol[j] = __float2half_rn(v - __half2float(h));
    } else if (i < QKV_N + WO_N + W1_N) {
        int j = i - QKV_N - WO_N;
        float v = w1[j];
        __half h = __float2half_rn(v);
        w1h[j] = h;
        w1l[j] = __float2half_rn(v - __half2float(h));
    } else if (i < QKV_N + WO_N + W1_N + W2_N) {
        int j = i - QKV_N - WO_N - W1_N;
        w2h[j] = __float2half_rn(w2[j]);    // hi only
    }
}

// ---------------- block reduction (512 threads) ----------------
__device__ __forceinline__ float block_sum(float v, float* red) {
    int lane = threadIdx.x & 31, w = threadIdx.x >> 5;
    #pragma unroll
    for (int off = 16; off; off >>= 1) v += __shfl_down_sync(0xffffffffu, v, off);
    __syncthreads();
    if (lane == 0) red[w] = v;
    __syncthreads();
    if (threadIdx.x < 32) {
        float t = (threadIdx.x < 16) ? red[threadIdx.x] : 0.f;
        #pragma unroll
        for (int off = 8; off; off >>= 1) t += __shfl_down_sync(0xffffffffu, t, off);
        if (threadIdx.x == 0) red[32] = t;
    }
    __syncthreads();
    return red[32];
}

// ---------------- LayerNorm + LIF over time (per (b,n) row) ----------------
__global__ void ln_lif_kernel(const float* __restrict__ x,
                              const float* __restrict__ g,
                              const float* __restrict__ bia,
                              __half* __restrict__ sp,
                              unsigned long long* __restrict__ counter) {
    __shared__ float red[33];
    int bn = blockIdx.x;
    int b  = bn / Nn, n = bn % Nn;
    int d  = threadIdx.x;
    float gg = g[d], bb = bia[d];
    float mem = 0.f;
    float cnt = 0.f;
    for (int t = 0; t < Tt; ++t) {
        size_t rowoff = ((((size_t)b*Tt + t)*Nn) + n)*Dd;
        float v = x[rowoff + d];
        float mean = block_sum(v, red) * (1.f/Dd);
        float diff = v - mean;
        float var = block_sum(diff*diff, red) * (1.f/Dd);
        float h = diff * rsqrtf(var + 1e-5f) * gg + bb;
        mem = BETA*mem + h;
        float s = (mem >= 1.0f) ? 1.f : 0.f;
        mem -= s;
        sp[rowoff + d] = __float2half_rn(s);
        cnt += s;
    }
    float tot = block_sum(cnt, red);
    if (d == 0) atomicAdd(counter, (unsigned long long)(tot + 0.5f));
}

// ---------------- LIF over time axis: fp32 src -> binary fp16 spikes ----------------
__global__ void lif_time_kernel(const float* __restrict__ src, __half* __restrict__ dst,
                                int inner_sz, float thr,
                                unsigned long long* __restrict__ counter) {
    long long total = (long long)Bb * inner_sz;
    long long idx = (long long)blockIdx.x*blockDim.x + threadIdx.x;
    int cnt = 0;
    if (idx < total) {
        long long b = idx / inner_sz, r = idx % inner_sz;
        const float* p = src + (size_t)b*Tt*inner_sz + r;
        __half* q = dst + (size_t)b*Tt*inner_sz + r;
        float mem = 0.f;
        #pragma unroll
        for (int t = 0; t < Tt; ++t) {
            float v2 = p[(size_t)t*inner_sz];
            mem = BETA*mem + v2;
            float s = (mem >= thr) ? 1.f : 0.f;
            q[(size_t)t*inner_sz] = __float2half_rn(s);
            mem -= s*thr;
            cnt += (int)s;
        }
    }
    #pragma unroll
    for (int off = 16; off; off >>= 1) cnt += __shfl_down_sync(0xffffffffu, cnt, off);
    if ((threadIdx.x & 31) == 0 && cnt) atomicAdd(counter, (unsigned long long)cnt);
}

// ---------------- fp16 MMA primitives ----------------
__device__ __forceinline__ uint32_t cvta_sh(const void* p) {
    return (uint32_t)__cvta_generic_to_shared(p);
}
__device__ __forceinline__ void ldsm4(uint32_t* r, uint32_t addr) {
    asm volatile("ldmatrix.sync.aligned.m8n8.x4.shared.b16 {%0,%1,%2,%3}, [%4];\n"
        : "=r"(r[0]), "=r"(r[1]), "=r"(r[2]), "=r"(r[3]) : "r"(addr));
}
__device__ __forceinline__ void ldsm4t(uint32_t* r, uint32_t addr) {
    asm volatile("ldmatrix.sync.aligned.m8n8.x4.trans.shared.b16 {%0,%1,%2,%3}, [%4];\n"
        : "=r"(r[0]), "=r"(r[1]), "=r"(r[2]), "=r"(r[3]) : "r"(addr));
}
__device__ __forceinline__ void mma16816(float* c, const uint32_t* a, const uint32_t* b) {
    asm volatile("mma.sync.aligned.m16n8k16.row.col.f32.f16.f16.f32 "
        "{%0,%1,%2,%3},{%4,%5,%6,%7},{%8,%9},{%0,%1,%2,%3};\n"
        : "+f"(c[0]), "+f"(c[1]), "+f"(c[2]), "+f"(c[3])
        : "r"(a[0]), "r"(a[1]), "r"(a[2]), "r"(a[3]), "r"(b[0]), "r"(b[1]));
}
__device__ __forceinline__ void cp16(void* smem, const void* gmem) {
    asm volatile("cp.async.cg.shared.global [%0], [%1], 16;\n"
        :: "r"(cvta_sh(smem)), "l"(gmem));
}
#define CP_COMMIT() asm volatile("cp.async.commit_group;\n")
template<int N>
__device__ __forceinline__ void cp_wait() {
    asm volatile("cp.async.wait_group %0;\n" :: "n"(N));
}

// ---------------- split-fp16 MMA GEMM, BK=64, single fp32 accumulator ----------------
// C = (Ahi@Bhi [+ Ahi@Blo] [+ Alo@Bhi]) * outscale [+ R]   (lo operands are raw residuals)
// Block tile 128 x TN (TN=128 or 64), BK=64, 256 threads, warp grid 2x4 (64M x TN/4).
// BT=true : B is k-major [K x N] row-major, ldmatrix.trans
// BT=false: B is n-major [N x K] row-major (C = A@B^T), ldmatrix
template<bool HAS_ALO, bool HAS_BLO, bool BT, bool SPLIT_OUT, bool HAS_RES, int TN, int NS>
__global__ void __launch_bounds__(256, 2)
mma_gemm(const __half* __restrict__ Ah, const __half* __restrict__ Al,
         const __half* __restrict__ Bh, const __half* __restrict__ Bl,
         const float* __restrict__ R, float* __restrict__ Cf,
         __half* __restrict__ Ch, __half* __restrict__ Cl,
         int K, int lda, int ldb, int ldc,
         int zdiv,
         long long sA1, long long sA2,
         long long sB1, long long sB2,
         long long sC1, long long sC2,
         float outscale)
{
    extern __shared__ __half sm[];
    constexpr int AH_SZ  = 128*72;                          // 9216 halves (BK=64, pitch 72)
    constexpr int A_SZ   = HAS_ALO ? 2*AH_SZ : AH_SZ;
    constexpr int BPITCH = BT ? (TN + 8) : 72;
    constexpr int B_SZ   = BT ? 64*BPITCH : TN*72;          // per hi/lo tile
    constexpr int NB     = HAS_BLO ? 2 : 1;
    constexpr int STAGE  = A_SZ + NB*B_SZ;
    constexpr int WN     = TN/4;                            // per-warp N width (32 or 16)
    constexpr int NH     = WN/16;                           // 16-col ldsm groups (2 or 1)
    constexpr int NJ     = 2*NH;                            // 8-col mma tiles
    constexpr int MI     = 4;                               // 64 M rows per warp / 16
    constexpr int BCH    = TN/32;                           // B chunk iters (4 or 2)

    int tid = threadIdx.x, lane = tid & 31, wid = tid >> 5;
    int wm = (wid >> 2) * 64, wn = (wid & 3) * WN;
    int bm0 = blockIdx.y * 128, bn0 = blockIdx.x * TN;
    int z = blockIdx.z, z1 = z / zdiv, z2 = z % zdiv;
    size_t aoff = (size_t)z1*sA1 + (size_t)z2*sA2;
    size_t boff = (size_t)z1*sB1 + (size_t)z2*sB2;
    size_t coff = (size_t)z1*sC1 + (size_t)z2*sC2;

    float acc[MI][NJ][4] = {};

    auto load_stage = [&](int k0, int st) {
        __half* base = sm + st*STAGE;
        #pragma unroll
        for (int i = 0; i < 4; i++) {                    // 1024 A chunks of 8 halves
            int idx = tid + i*256;
            int row = idx >> 3, col = (idx & 7) << 3;
            cp16(&base[row*72 + col],
                 Ah + aoff + (size_t)(bm0+row)*lda + k0 + col);
            if (HAS_ALO)
                cp16(&base[AH_SZ + row*72 + col],
                     Al + aoff + (size_t)(bm0+row)*lda + k0 + col);
        }
        __half* sBh = base + A_SZ;
        __half* sBl = sBh + B_SZ;
        #pragma unroll
        for (int i = 0; i < BCH; i++) {
            int idx = tid + i*256;
            if (BT) {
                int row = idx / (TN/8), col = (idx % (TN/8)) << 3;   // 64 x TN
                const __half* gh = Bh + boff + (size_t)(k0+row)*ldb + bn0 + col;
                cp16(&sBh[row*BPITCH + col], gh);
                if (HAS_BLO)
                    cp16(&sBl[row*BPITCH + col], Bl + boff + (size_t)(k0+row)*ldb + bn0 + col);
            } else {
                int row = idx >> 3, col = (idx & 7) << 3;            // TN x 64
                cp16(&sBh[row*72 + col], Bh + boff + (size_t)(bn0+row)*ldb + k0 + col);
                if (HAS_BLO)
                    cp16(&sBl[row*72 + col], Bl + boff + (size_t)(bn0+row)*ldb + k0 + col);
            }
        }
        CP_COMMIT();
    };

    // prologue (uniform commit cadence)
    #pragma unroll
    for (int s = 0; s < NS-1; s++) {
        if (s*64 < K) load_stage(s*64, s);
        else CP_COMMIT();
    }

    int it = 0;
    for (int k0 = 0; k0 < K; k0 += 64, ++it) {
        int kpre = k0 + (NS-1)*64;
        if (kpre < K) load_stage(kpre, (it + NS-1) % NS);
        else CP_COMMIT();

        cp_wait<NS-1>();
        __syncthreads();

        __half* base = sm + (it % NS)*STAGE;
        __half* sAh = base;
        __half* sAl = base + AH_SZ;
        __half* sBh = base + A_SZ;
        __half* sBl = sBh + B_SZ;

        #pragma unroll
        for (int kk = 0; kk < 64; kk += 16) {
            uint32_t afh[MI][4], afl[MI][4];
            #pragma unroll
            for (int mi = 0; mi < MI; mi++) {
                int row = wm + mi*16 + (lane & 15);
                int col = kk + ((lane >> 4) << 3);
                ldsm4(afh[mi], cvta_sh(&sAh[row*72 + col]));
                if (HAS_ALO) ldsm4(afl[mi], cvta_sh(&sAl[row*72 + col]));
            }
            uint32_t bfh[NH][4], bfl[NH][4];
            int g = lane >> 3, rr = lane & 7;
            #pragma unroll
            for (int nh = 0; nh < NH; nh++) {
                if (BT) {
                    int krow = kk + (g & 1)*8 + rr;
                    int ncol = wn + nh*16 + (g >> 1)*8;
                    ldsm4t(bfh[nh], cvta_sh(&sBh[krow*BPITCH + ncol]));
                    if (HAS_BLO) ldsm4t(bfl[nh], cvta_sh(&sBl[krow*BPITCH + ncol]));
                } else {
                    int nrow = wn + nh*16 + (g >> 1)*8 + rr;
                    int kcol = kk + (g & 1)*8;
                    ldsm4(bfh[nh], cvta_sh(&sBh[nrow*72 + kcol]));
                    if (HAS_BLO) ldsm4(bfl[nh], cvta_sh(&sBl[nrow*72 + kcol]));
                }
            }
            #pragma unroll
            for (int mi = 0; mi < MI; mi++)
                #pragma unroll
                for (int nh = 0; nh < NH; nh++)
                    #pragma unroll
                    for (int s = 0; s < 2; s++) {
                        int nj = nh*2 + s;
                        mma16816(acc[mi][nj], afh[mi], &bfh[nh][s*2]);
                        if (HAS_BLO) mma16816(acc[mi][nj], afh[mi], &bfl[nh][s*2]);
                        if (HAS_ALO) mma16816(acc[mi][nj], afl[mi], &bfh[nh][s*2]);
                    }
        }
        __syncthreads();
    }

    // ---- epilogue (vectorized pairs) ----
    #pragma unroll
    for (int mi = 0; mi < MI; mi++)
        #pragma unroll
        for (int nj = 0; nj < NJ; nj++) {
            int row0 = bm0 + wm + mi*16 + (lane >> 2);
            int col0 = bn0 + wn + nj*8 + ((lane & 3) << 1);
            #pragma unroll
            for (int hh = 0; hh < 2; hh++) {
                int row = row0 + hh*8;
                size_t off = coff + (size_t)row*ldc + col0;
                float v0 = acc[mi][nj][hh*2+0] * outscale;
                float v1 = acc[mi][nj][hh*2+1] * outscale;
                if (HAS_RES) {
                    float2 r2 = *(const float2*)(R + off);
                    v0 += r2.x; v1 += r2.y;
                }
                if (SPLIT_OUT) {
                    __half h0 = __float2half_rn(v0), h1 = __float2half_rn(v1);
                    *(__half2*)(Ch + off) = __halves2half2(h0, h1);
                    *(__half2*)(Cl + off) = __halves2half2(
                        __float2half_rn(v0 - __half2float(h0)),
                        __float2half_rn(v1 - __half2float(h1)));
                } else {
                    *(float2*)(Cf + off) = make_float2(v0, v1);
                }
            }
        }
}

// ---------------- write the 4 spike-rate scalars ----------------
__global__ void finalize_kernel(float* __restrict__ out, long long out_size) {
    if (out_size >= (long long)BTND + 4) {
        out[BTND+0] = (float)((double)g_cnt[0] / 4194304.0);   // r_lif1
        out[BTND+1] = (float)((double)g_cnt[1] / 16777216.0);  // r_attn
        out[BTND+2] = (float)((double)g_cnt[2] / 4194304.0);   // r_lif2
        out[BTND+3] = (float)((double)g_cnt[3] / 16777216.0);  // r_ffn
    }
}

// ---------------- host launcher ----------------
extern "C" void kernel_launch(void* const* d_in, const int* in_sizes, int n_in,
                              void* d_out, int out_size) {
    const float* x  = (const float*)d_in[0];
    const float* g1 = (const float*)d_in[1];
    const float* b1 = (const float*)d_in[2];
    const float* wq = (const float*)d_in[3];
    const float* wk = (const float*)d_in[4];
    const float* wv = (const float*)d_in[5];
    const float* wo = (const float*)d_in[6];
    const float* g2 = (const float*)d_in[7];
    const float* b2 = (const float*)d_in[8];
    const float* w1 = (const float*)d_in[9];
    const float* w2 = (const float*)d_in[10];
    float* out = (float*)d_out;

    __half *s1h, *qkvh, *qkvl, *sah, *aoh, *aol, *s2h, *hsh;
    __half *wqkvh,*wqkvl,*woh,*wol,*w1h,*w1l,*w2h;
    float *sc, *xm, *hid;
    unsigned long long* cnt;
    cudaGetSymbolAddress((void**)&s1h,  g_s1h);
    cudaGetSymbolAddress((void**)&qkvh, g_qkvh); cudaGetSymbolAddress((void**)&qkvl, g_qkvl);
    cudaGetSymbolAddress((void**)&sc,   g_scores);
    cudaGetSymbolAddress((void**)&sah,  g_sah);
    cudaGetSymbolAddress((void**)&aoh,  g_aoh);  cudaGetSymbolAddress((void**)&aol,  g_aol);
    cudaGetSymbolAddress((void**)&xm,   g_xm);
    cudaGetSymbolAddress((void**)&s2h,  g_s2h);
    cudaGetSymbolAddress((void**)&hid,  g_hid);
    cudaGetSymbolAddress((void**)&hsh,  g_hsh);
    cudaGetSymbolAddress((void**)&wqkvh,g_wqkvh);cudaGetSymbolAddress((void**)&wqkvl,g_wqkvl);
    cudaGetSymbolAddress((void**)&woh,  g_woh);  cudaGetSymbolAddress((void**)&wol,  g_wol);
    cudaGetSymbolAddress((void**)&w1h,  g_w1h);  cudaGetSymbolAddress((void**)&w1l,  g_w1l);
    cudaGetSymbolAddress((void**)&w2h,  g_w2h);
    cudaGetSymbolAddress((void**)&cnt,  g_cnt);

    // dynamic smem bytes (halves*2): stage sizes per config
    const int SMEM_QKV = 2*(128*72 + 2*64*136) * 2;          // 106496 (noALO,BLO,BT,TN128,NS2)
    const int SMEM_SCR = 1*(2*128*72 + 2*128*72) * 2;        // 73728  (ALO,BLO,!BT,TN128,NS1)
    const int SMEM_AO  = 2*(128*72 + 2*64*72) * 2;           // 73728  (noALO,BLO,BT,TN64,NS2)
    const int SMEM_WO  = 1*(2*128*72 + 2*64*136) * 2;        // 71680  (ALO,BLO,BT,TN128,NS1)
    const int SMEM_W1  = SMEM_QKV;                           // 106496
    const int SMEM_W2  = 2*(128*72 + 64*136) * 2;            // 71680  (noALO,noBLO,BT,TN128,NS2)

    cudaFuncSetAttribute(mma_gemm<false,true ,true ,true ,false,128,2>, cudaFuncAttributeMaxDynamicSharedMemorySize, SMEM_QKV);
    cudaFuncSetAttribute(mma_gemm<true ,true ,false,false,false,128,1>, cudaFuncAttributeMaxDynamicSharedMemorySize, SMEM_SCR);
    cudaFuncSetAttribute(mma_gemm<false,true ,true ,true ,false,64 ,2>, cudaFuncAttributeMaxDynamicSharedMemorySize, SMEM_AO);
    cudaFuncSetAttribute(mma_gemm<true ,true ,true ,false,true ,128,1>, cudaFuncAttributeMaxDynamicSharedMemorySize, SMEM_WO);
    cudaFuncSetAttribute(mma_gemm<false,true ,true ,false,false,128,2>, cudaFuncAttributeMaxDynamicSharedMemorySize, SMEM_W1);
    cudaFuncSetAttribute(mma_gemm<false,false,true ,false,true ,128,2>, cudaFuncAttributeMaxDynamicSharedMemorySize, SMEM_W2);

    zero_cnt_kernel<<<1, 32>>>();

    // all weight splits in one launch
    split_all_kernel<<<(3*Dd*Dd + Dd*Dd + 2*Dd*HIDd + 255)/256, 256>>>(
        wq, wk, wv, wo, w1, w2,
        wqkvh, wqkvl, woh, wol, w1h, w1l, w2h);

    // ---- attention branch ----
    ln_lif_kernel<<<Bb*Nn, 512>>>(x, g1, b1, s1h, cnt + 0);

    // fused QKV: binary A (s1) @ [wq|wk|wv], split outputs into qkv buffer
    mma_gemm<false,true,true,true,false,128,2><<<dim3(QKVW/128, BTN/128), 256, SMEM_QKV>>>(
        s1h, nullptr, wqkvh, wqkvl, nullptr, nullptr, qkvh, qkvl,
        Dd, Dd, QKVW, QKVW, 1, 0,0, 0,0, 0,0, 1.f);

    // scores = 0.125 * q @ k^T (batched over B*T*H), 3-term, K=64 single chunk
    mma_gemm<true,true,false,false,false,128,1><<<dim3(Nn/128, Nn/128, Bb*Tt*Hh), 256, SMEM_SCR>>>(
        qkvh, qkvl, qkvh + Dd, qkvl + Dd, nullptr, sc, nullptr, nullptr,
        DHh, QKVW, QKVW, Nn,
        Hh, (long long)Nn*QKVW, 64LL, (long long)Nn*QKVW, 64LL,
        (long long)Hh*Nn*Nn, (long long)Nn*Nn, 0.125f);

    lif_time_kernel<<<16384, 256>>>(sc, sah, Hh*Nn*Nn, 0.5f, cnt + 1);

    // attnout = sa @ v (batched), binary A, split B = v slice of qkv
    mma_gemm<false,true,true,true,false,64,2><<<dim3(DHh/64, Nn/128, Bb*Tt*Hh), 256, SMEM_AO>>>(
        sah, nullptr, qkvh + 2*Dd, qkvl + 2*Dd, nullptr, nullptr, aoh, aol,
        Nn, Nn, QKVW, Dd,
        Hh, (long long)Hh*Nn*Nn, (long long)Nn*Nn,
        (long long)Nn*QKVW, 64LL, (long long)Nn*Dd, 64LL, 1.f);

    // xm = x + ao @ wo  (3-term)
    mma_gemm<true,true,true,false,true,128,1><<<dim3(Dd/128, BTN/128), 256, SMEM_WO>>>(
        aoh, aol, woh, wol, x, xm, nullptr, nullptr,
        Dd, Dd, Dd, Dd, 1, 0,0, 0,0, 0,0, 1.f);

    // ---- MLP branch ----
    ln_lif_kernel<<<Bb*Nn, 512>>>(xm, g2, b2, s2h, cnt + 2);

    // hid = s2 @ w1 (2-term, exact: feeds LIF)
    mma_gemm<false,true,true,false,false,128,2><<<dim3(HIDd/128, BTN/128), 256, SMEM_W1>>>(
        s2h, nullptr, w1h, w1l, nullptr, hid, nullptr, nullptr,
        Dd, Dd, HIDd, HIDd, 1, 0,0, 0,0, 0,0, 1.f);

    lif_time_kernel<<<16384, 256>>>(hid, hsh, Nn*HIDd, 1.0f, cnt + 3);

    // out = xm + hs @ w2 (1-term: final layer, no LIF downstream)
    mma_gemm<false,false,true,false,true,128,2><<<dim3(Dd/128, BTN/128), 256, SMEM_W2>>>(
        hsh, nullptr, w2h, nullptr, xm, out, nullptr, nullptr,
        HIDd, HIDd, Dd, Dd, 1, 0,0, 0,0, 0,0, 1.f);

    finalize_kernel<<<1, 1>>>(out, (long long)out_size);
}

// round 14
// speedup vs baseline: 1.4690x; 1.0321x over previous
#include <cuda_runtime.h>
#include <cuda_fp16.h>
#include <cstdint>

// ---------------- problem dims ----------------
#define Bb   8
#define Tt   4
#define Nn   256
#define Dd   512
#define Hh   8
#define DHh  64
#define HIDd 2048
#define BTN  (Bb*Tt*Nn)            // 8192 rows
#define BTND ((size_t)BTN*Dd)      // 4194304
#define SCORES_ELEMS ((size_t)Bb*Tt*Hh*Nn*Nn)  // 16777216
#define HID_ELEMS    ((size_t)BTN*HIDd)        // 16777216
#define QKVW (3*Dd)                // 1536

#define BETA 0.95122942450071403f  // fp32(exp(-1/20))

// ---------------- scratch (static device globals; no allocation) ----------------
__device__ __half g_s1h[BTND];
__device__ __half g_qkvh[(size_t)BTN*QKVW], g_qkvl[(size_t)BTN*QKVW];
__device__ __half g_sah[SCORES_ELEMS];
__device__ __half g_aoh[BTND], g_aol[BTND];
__device__ float  g_xm[BTND];
__device__ __half g_s2h[BTND];
__device__ float  g_hid[HID_ELEMS];
__device__ __half g_hsh[HID_ELEMS];
// weight splits (residual lo stored UNSCALED)
__device__ __half g_wqkvh[Dd*QKVW], g_wqkvl[Dd*QKVW];
__device__ __half g_woh[Dd*Dd], g_wol[Dd*Dd];
__device__ __half g_w1h[Dd*HIDd], g_w1l[Dd*HIDd];
__device__ __half g_w2h[HIDd*Dd];                 // w2 lo dropped (last layer, no LIF after)
__device__ unsigned long long g_cnt[4];

// ---------------- counters ----------------
__global__ void zero_cnt_kernel() {
    if (threadIdx.x < 4) g_cnt[threadIdx.x] = 0ULL;
}

// ---------------- all weight splits in one launch ----------------
__global__ void split_all_kernel(const float* __restrict__ wq,
                                 const float* __restrict__ wk,
                                 const float* __restrict__ wv,
                                 const float* __restrict__ wo,
                                 const float* __restrict__ w1,
                                 const float* __restrict__ w2,
                                 __half* __restrict__ qkvh, __half* __restrict__ qkvl,
                                 __half* __restrict__ woh,  __half* __restrict__ wol,
                                 __half* __restrict__ w1h,  __half* __restrict__ w1l,
                                 __half* __restrict__ w2h) {
    int i = blockIdx.x*blockDim.x + threadIdx.x;
    const int QKV_N = 3*Dd*Dd;
    const int WO_N  = Dd*Dd;
    const int W1_N  = Dd*HIDd;
    const int W2_N  = HIDd*Dd;
    if (i < QKV_N) {
        int which = i / (Dd*Dd);
        int rem = i % (Dd*Dd);
        int r = rem / Dd, c = rem % Dd;
        const float* src = (which == 0) ? wq : (which == 1) ? wk : wv;
        float v = src[rem];
        __half h = __float2half_rn(v);
        size_t off = (size_t)r*QKVW + which*Dd + c;
        qkvh[off] = h;
        qkvl[off] = __float2half_rn(v - __half2float(h));
    } else if (i < QKV_N + WO_N) {
        int j = i - QKV_N;
        float v = wo[j];
        __half h = __float2half_rn(v);
        woh[j] = h;
        wol[j] = __float2half_rn(v - __half2float(h));
    } else if (i < QKV_N + WO_N + W1_N) {
        int j = i - QKV_N - WO_N;
        float v = w1[j];
        __half h = __float2half_rn(v);
        w1h[j] = h;
        w1l[j] = __float2half_rn(v - __half2float(h));
    } else if (i < QKV_N + WO_N + W1_N + W2_N) {
        int j = i - QKV_N - WO_N - W1_N;
        w2h[j] = __float2half_rn(w2[j]);    // hi only
    }
}

// ---------------- block reduction (512 threads) ----------------
__device__ __forceinline__ float block_sum(float v, float* red) {
    int lane = threadIdx.x & 31, w = threadIdx.x >> 5;
    #pragma unroll
    for (int off = 16; off; off >>= 1) v += __shfl_down_sync(0xffffffffu, v, off);
    __syncthreads();
    if (lane == 0) red[w] = v;
    __syncthreads();
    if (threadIdx.x < 32) {
        float t = (threadIdx.x < 16) ? red[threadIdx.x] : 0.f;
        #pragma unroll
        for (int off = 8; off; off >>= 1) t += __shfl_down_sync(0xffffffffu, t, off);
        if (threadIdx.x == 0) red[32] = t;
    }
    __syncthreads();
    return red[32];
}

// ---------------- LayerNorm + LIF over time (per (b,n) row) ----------------
__global__ void ln_lif_kernel(const float* __restrict__ x,
                              const float* __restrict__ g,
                              const float* __restrict__ bia,
                              __half* __restrict__ sp,
                              unsigned long long* __restrict__ counter) {
    __shared__ float red[33];
    int bn = blockIdx.x;
    int b  = bn / Nn, n = bn % Nn;
    int d  = threadIdx.x;
    float gg = g[d], bb = bia[d];
    float mem = 0.f;
    float cnt = 0.f;
    for (int t = 0; t < Tt; ++t) {
        size_t rowoff = ((((size_t)b*Tt + t)*Nn) + n)*Dd;
        float v = x[rowoff + d];
        float mean = block_sum(v, red) * (1.f/Dd);
        float diff = v - mean;
        float var = block_sum(diff*diff, red) * (1.f/Dd);
        float h = diff * rsqrtf(var + 1e-5f) * gg + bb;
        mem = BETA*mem + h;
        float s = (mem >= 1.0f) ? 1.f : 0.f;
        mem -= s;
        sp[rowoff + d] = __float2half_rn(s);
        cnt += s;
    }
    float tot = block_sum(cnt, red);
    if (d == 0) atomicAdd(counter, (unsigned long long)(tot + 0.5f));
}

// ---------------- LIF over time axis: fp32 src -> binary fp16 spikes ----------------
__global__ void lif_time_kernel(const float* __restrict__ src, __half* __restrict__ dst,
                                int inner_sz, float thr,
                                unsigned long long* __restrict__ counter) {
    long long total = (long long)Bb * inner_sz;
    long long idx = (long long)blockIdx.x*blockDim.x + threadIdx.x;
    int cnt = 0;
    if (idx < total) {
        long long b = idx / inner_sz, r = idx % inner_sz;
        const float* p = src + (size_t)b*Tt*inner_sz + r;
        __half* q = dst + (size_t)b*Tt*inner_sz + r;
        float mem = 0.f;
        #pragma unroll
        for (int t = 0; t < Tt; ++t) {
            float v2 = p[(size_t)t*inner_sz];
            mem = BETA*mem + v2;
            float s = (mem >= thr) ? 1.f : 0.f;
            q[(size_t)t*inner_sz] = __float2half_rn(s);
            mem -= s*thr;
            cnt += (int)s;
        }
    }
    #pragma unroll
    for (int off = 16; off; off >>= 1) cnt += __shfl_down_sync(0xffffffffu, cnt, off);
    if ((threadIdx.x & 31) == 0 && cnt) atomicAdd(counter, (unsigned long long)cnt);
}

// ---------------- fp16 MMA primitives ----------------
__device__ __forceinline__ uint32_t cvta_sh(const void* p) {
    return (uint32_t)__cvta_generic_to_shared(p);
}
__device__ __forceinline__ void ldsm4(uint32_t* r, uint32_t addr) {
    asm volatile("ldmatrix.sync.aligned.m8n8.x4.shared.b16 {%0,%1,%2,%3}, [%4];\n"
        : "=r"(r[0]), "=r"(r[1]), "=r"(r[2]), "=r"(r[3]) : "r"(addr));
}
__device__ __forceinline__ void ldsm4t(uint32_t* r, uint32_t addr) {
    asm volatile("ldmatrix.sync.aligned.m8n8.x4.trans.shared.b16 {%0,%1,%2,%3}, [%4];\n"
        : "=r"(r[0]), "=r"(r[1]), "=r"(r[2]), "=r"(r[3]) : "r"(addr));
}
__device__ __forceinline__ void mma16816(float* c, const uint32_t* a, const uint32_t* b) {
    asm volatile("mma.sync.aligned.m16n8k16.row.col.f32.f16.f16.f32 "
        "{%0,%1,%2,%3},{%4,%5,%6,%7},{%8,%9},{%0,%1,%2,%3};\n"
        : "+f"(c[0]), "+f"(c[1]), "+f"(c[2]), "+f"(c[3])
        : "r"(a[0]), "r"(a[1]), "r"(a[2]), "r"(a[3]), "r"(b[0]), "r"(b[1]));
}
__device__ __forceinline__ void cp16(void* smem, const void* gmem) {
    asm volatile("cp.async.cg.shared.global [%0], [%1], 16;\n"
        :: "r"(cvta_sh(smem)), "l"(gmem));
}
#define CP_COMMIT() asm volatile("cp.async.commit_group;\n")
template<int N>
__device__ __forceinline__ void cp_wait() {
    asm volatile("cp.async.wait_group %0;\n" :: "n"(N));
}

// ---------------- split-fp16 MMA GEMM, BK=64, single fp32 accumulator ----------------
// C = (Ahi@Bhi [+ Ahi@Blo] [+ Alo@Bhi]) * outscale [+ R]
// Block tile 128 x TN, BK=64, 256 threads, warp grid 2x4 (64M x TN/4).
// MMA issue order: full hi sweep, then lo sweeps (long RAW distance per acc).
template<bool HAS_ALO, bool HAS_BLO, bool BT, bool SPLIT_OUT, bool HAS_RES, int TN, int NS>
__global__ void __launch_bounds__(256, 2)
mma_gemm(const __half* __restrict__ Ah, const __half* __restrict__ Al,
         const __half* __restrict__ Bh, const __half* __restrict__ Bl,
         const float* __restrict__ R, float* __restrict__ Cf,
         __half* __restrict__ Ch, __half* __restrict__ Cl,
         int K, int lda, int ldb, int ldc,
         int zdiv,
         long long sA1, long long sA2,
         long long sB1, long long sB2,
         long long sC1, long long sC2,
         float outscale)
{
    extern __shared__ __half sm[];
    constexpr int AH_SZ  = 128*72;
    constexpr int A_SZ   = HAS_ALO ? 2*AH_SZ : AH_SZ;
    constexpr int BPITCH = BT ? (TN + 8) : 72;
    constexpr int B_SZ   = BT ? 64*BPITCH : TN*72;
    constexpr int NB     = HAS_BLO ? 2 : 1;
    constexpr int STAGE  = A_SZ + NB*B_SZ;
    constexpr int WN     = TN/4;
    constexpr int NH     = WN/16;
    constexpr int NJ     = 2*NH;
    constexpr int MI     = 4;
    constexpr int BCH    = TN/32;

    int tid = threadIdx.x, lane = tid & 31, wid = tid >> 5;
    int wm = (wid >> 2) * 64, wn = (wid & 3) * WN;
    int bm0 = blockIdx.y * 128, bn0 = blockIdx.x * TN;
    int z = blockIdx.z, z1 = z / zdiv, z2 = z % zdiv;
    size_t aoff = (size_t)z1*sA1 + (size_t)z2*sA2;
    size_t boff = (size_t)z1*sB1 + (size_t)z2*sB2;
    size_t coff = (size_t)z1*sC1 + (size_t)z2*sC2;

    float acc[MI][NJ][4] = {};

    auto load_stage = [&](int k0, int st) {
        __half* base = sm + st*STAGE;
        #pragma unroll
        for (int i = 0; i < 4; i++) {
            int idx = tid + i*256;
            int row = idx >> 3, col = (idx & 7) << 3;
            cp16(&base[row*72 + col],
                 Ah + aoff + (size_t)(bm0+row)*lda + k0 + col);
            if (HAS_ALO)
                cp16(&base[AH_SZ + row*72 + col],
                     Al + aoff + (size_t)(bm0+row)*lda + k0 + col);
        }
        __half* sBh = base + A_SZ;
        __half* sBl = sBh + B_SZ;
        #pragma unroll
        for (int i = 0; i < BCH; i++) {
            int idx = tid + i*256;
            if (BT) {
                int row = idx / (TN/8), col = (idx % (TN/8)) << 3;
                cp16(&sBh[row*BPITCH + col], Bh + boff + (size_t)(k0+row)*ldb + bn0 + col);
                if (HAS_BLO)
                    cp16(&sBl[row*BPITCH + col], Bl + boff + (size_t)(k0+row)*ldb + bn0 + col);
            } else {
                int row = idx >> 3, col = (idx & 7) << 3;
                cp16(&sBh[row*72 + col], Bh + boff + (size_t)(bn0+row)*ldb + k0 + col);
                if (HAS_BLO)
                    cp16(&sBl[row*72 + col], Bl + boff + (size_t)(bn0+row)*ldb + k0 + col);
            }
        }
        CP_COMMIT();
    };

    #pragma unroll
    for (int s = 0; s < NS-1; s++) {
        if (s*64 < K) load_stage(s*64, s);
        else CP_COMMIT();
    }

    int it = 0;
    for (int k0 = 0; k0 < K; k0 += 64, ++it) {
        int kpre = k0 + (NS-1)*64;
        if (kpre < K) load_stage(kpre, (it + NS-1) % NS);
        else CP_COMMIT();

        cp_wait<NS-1>();
        __syncthreads();

        __half* base = sm + (it % NS)*STAGE;
        __half* sAh = base;
        __half* sAl = base + AH_SZ;
        __half* sBh = base + A_SZ;
        __half* sBl = sBh + B_SZ;

        #pragma unroll
        for (int kk = 0; kk < 64; kk += 16) {
            uint32_t afh[MI][4], afl[MI][4];
            #pragma unroll
            for (int mi = 0; mi < MI; mi++) {
                int row = wm + mi*16 + (lane & 15);
                int col = kk + ((lane >> 4) << 3);
                ldsm4(afh[mi], cvta_sh(&sAh[row*72 + col]));
                if (HAS_ALO) ldsm4(afl[mi], cvta_sh(&sAl[row*72 + col]));
            }
            uint32_t bfh[NH][4], bfl[NH][4];
            int g = lane >> 3, rr = lane & 7;
            #pragma unroll
            for (int nh = 0; nh < NH; nh++) {
                if (BT) {
                    int krow = kk + (g & 1)*8 + rr;
                    int ncol = wn + nh*16 + (g >> 1)*8;
                    ldsm4t(bfh[nh], cvta_sh(&sBh[krow*BPITCH + ncol]));
                    if (HAS_BLO) ldsm4t(bfl[nh], cvta_sh(&sBl[krow*BPITCH + ncol]));
                } else {
                    int nrow = wn + nh*16 + (g >> 1)*8 + rr;
                    int kcol = kk + (g & 1)*8;
                    ldsm4(bfh[nh], cvta_sh(&sBh[nrow*72 + kcol]));
                    if (HAS_BLO) ldsm4(bfl[nh], cvta_sh(&sBl[nrow*72 + kcol]));
                }
            }
            // pass 1: hi (all acc touched once)
            #pragma unroll
            for (int mi = 0; mi < MI; mi++)
                #pragma unroll
                for (int nh = 0; nh < NH; nh++)
                    #pragma unroll
                    for (int s = 0; s < 2; s++)
                        mma16816(acc[mi][nh*2+s], afh[mi], &bfh[nh][s*2]);
            // pass 2: B-lo
            if (HAS_BLO) {
                #pragma unroll
                for (int mi = 0; mi < MI; mi++)
                    #pragma unroll
                    for (int nh = 0; nh < NH; nh++)
                        #pragma unroll
                        for (int s = 0; s < 2; s++)
                            mma16816(acc[mi][nh*2+s], afh[mi], &bfl[nh][s*2]);
            }
            // pass 3: A-lo
            if (HAS_ALO) {
                #pragma unroll
                for (int mi = 0; mi < MI; mi++)
                    #pragma unroll
                    for (int nh = 0; nh < NH; nh++)
                        #pragma unroll
                        for (int s = 0; s < 2; s++)
                            mma16816(acc[mi][nh*2+s], afl[mi], &bfh[nh][s*2]);
            }
        }
        __syncthreads();
    }

    // ---- epilogue (vectorized pairs) ----
    #pragma unroll
    for (int mi = 0; mi < MI; mi++)
        #pragma unroll
        for (int nj = 0; nj < NJ; nj++) {
            int row0 = bm0 + wm + mi*16 + (lane >> 2);
            int col0 = bn0 + wn + nj*8 + ((lane & 3) << 1);
            #pragma unroll
            for (int hh = 0; hh < 2; hh++) {
                int row = row0 + hh*8;
                size_t off = coff + (size_t)row*ldc + col0;
                float v0 = acc[mi][nj][hh*2+0] * outscale;
                float v1 = acc[mi][nj][hh*2+1] * outscale;
                if (HAS_RES) {
                    float2 r2 = *(const float2*)(R + off);
                    v0 += r2.x; v1 += r2.y;
                }
                if (SPLIT_OUT) {
                    __half h0 = __float2half_rn(v0), h1 = __float2half_rn(v1);
                    *(__half2*)(Ch + off) = __halves2half2(h0, h1);
                    *(__half2*)(Cl + off) = __halves2half2(
                        __float2half_rn(v0 - __half2float(h0)),
                        __float2half_rn(v1 - __half2float(h1)));
                } else {
                    *(float2*)(Cf + off) = make_float2(v0, v1);
                }
            }
        }
}

// ---------------- fused scores GEMM + attention LIF ----------------
// grid (Nn/128, Nn/128, Bb*Hh), 512 threads (16 warps, 4x4, warp tile 32x32).
// For each t: scores_tile = 0.125*(qh@kh^T + qh@kl^T + ql@kh^T); LIF(thr=0.5)
// in registers across t; emits binary spikes (half) directly to sah[b,t,h,n,m].
__global__ void __launch_bounds__(512, 1)
scores_lif_kernel(const __half* __restrict__ qkvh, const __half* __restrict__ qkvl,
                  __half* __restrict__ sah, unsigned long long* __restrict__ counter)
{
    extern __shared__ __half sm[];
    constexpr int PITCH = 72;
    constexpr int T_SZ  = 128*PITCH;      // one 128x64 tile (pitch 72)
    constexpr int STAGE = 4*T_SZ;         // q-hi, q-lo, k-hi, k-lo

    int tid = threadIdx.x, lane = tid & 31, wid = tid >> 5;
    int wm = (wid >> 2) * 32, wn = (wid & 3) * 32;
    int n0 = blockIdx.y * 128, m0 = blockIdx.x * 128;
    int z = blockIdx.z, b = z / Hh, h = z % Hh;

    float mem[2][4][4] = {};
    int scnt = 0;

    auto load_t = [&](int t, int st) {
        __half* base = sm + st*STAGE;
        size_t qoff = ((size_t)((b*Tt + t)*Nn))*QKVW + h*DHh;
        size_t koff = qoff + Dd;
        #pragma unroll
        for (int i = 0; i < 2; i++) {
            int idx = tid + i*512;
            int row = idx >> 3, col = (idx & 7) << 3;
            cp16(&base[         row*PITCH + col], qkvh + qoff + (size_t)(n0+row)*QKVW + col);
            cp16(&base[T_SZ   + row*PITCH + col], qkvl + qoff + (size_t)(n0+row)*QKVW + col);
            cp16(&base[2*T_SZ + row*PITCH + col], qkvh + koff + (size_t)(m0+row)*QKVW + col);
            cp16(&base[3*T_SZ + row*PITCH + col], qkvl + koff + (size_t)(m0+row)*QKVW + col);
        }
        CP_COMMIT();
    };

    load_t(0, 0);
    for (int t = 0; t < Tt; t++) {
        if (t + 1 < Tt) { load_t(t + 1, (t + 1) & 1); cp_wait<1>(); }
        else           { CP_COMMIT();                 cp_wait<0>(); }
        __syncthreads();

        __half* base = sm + (t & 1)*STAGE;
        __half* sQh = base;
        __half* sQl = base + T_SZ;
        __half* sKh = base + 2*T_SZ;
        __half* sKl = base + 3*T_SZ;

        float acc[2][4][4] = {};
        #pragma unroll
        for (int kk = 0; kk < 64; kk += 16) {
            uint32_t afh[2][4], afl[2][4], bfh[2][4], bfl[2][4];
            #pragma unroll
            for (int mi = 0; mi < 2; mi++) {
                int row = wm + mi*16 + (lane & 15);
                int col = kk + ((lane >> 4) << 3);
                ldsm4(afh[mi], cvta_sh(&sQh[row*PITCH + col]));
                ldsm4(afl[mi], cvta_sh(&sQl[row*PITCH + col]));
            }
            int g = lane >> 3, rr = lane & 7;
            #pragma unroll
            for (int nh = 0; nh < 2; nh++) {
                int nrow = wn + nh*16 + (g >> 1)*8 + rr;
                int kcol = kk + (g & 1)*8;
                ldsm4(bfh[nh], cvta_sh(&sKh[nrow*PITCH + kcol]));
                ldsm4(bfl[nh], cvta_sh(&sKl[nrow*PITCH + kcol]));
            }
            #pragma unroll
            for (int mi = 0; mi < 2; mi++)
                #pragma unroll
                for (int nh = 0; nh < 2; nh++)
                    #pragma unroll
                    for (int s = 0; s < 2; s++)
                        mma16816(acc[mi][nh*2+s], afh[mi], &bfh[nh][s*2]);
            #pragma unroll
            for (int mi = 0; mi < 2; mi++)
                #pragma unroll
                for (int nh = 0; nh < 2; nh++)
                    #pragma unroll
                    for (int s = 0; s < 2; s++)
                        mma16816(acc[mi][nh*2+s], afh[mi], &bfl[nh][s*2]);
            #pragma unroll
            for (int mi = 0; mi < 2; mi++)
                #pragma unroll
                for (int nh = 0; nh < 2; nh++)
                    #pragma unroll
                    for (int s = 0; s < 2; s++)
                        mma16816(acc[mi][nh*2+s], afl[mi], &bfh[nh][s*2]);
        }

        // LIF step + spike write
        size_t zoff = ((size_t)((b*Tt + t)*Hh + h))*Nn*Nn;
        #pragma unroll
        for (int mi = 0; mi < 2; mi++)
            #pragma unroll
            for (int nj = 0; nj < 4; nj++) {
                int row0 = n0 + wm + mi*16 + (lane >> 2);
                int col0 = m0 + wn + nj*8 + ((lane & 3) << 1);
                #pragma unroll
                for (int hh = 0; hh < 2; hh++) {
                    float* M = &mem[mi][nj][hh*2];
                    float v0 = M[0]*BETA + 0.125f*acc[mi][nj][hh*2+0];
                    float v1 = M[1]*BETA + 0.125f*acc[mi][nj][hh*2+1];
                    float s0 = (v0 >= 0.5f) ? 1.f : 0.f;
                    float s1 = (v1 >= 0.5f) ? 1.f : 0.f;
                    M[0] = v0 - 0.5f*s0;
                    M[1] = v1 - 0.5f*s1;
                    scnt += (int)s0 + (int)s1;
                    size_t off = zoff + (size_t)(row0 + hh*8)*Nn + col0;
                    *(__half2*)(sah + off) =
                        __halves2half2(__float2half_rn(s0), __float2half_rn(s1));
                }
            }
        __syncthreads();
    }

    #pragma unroll
    for (int off = 16; off; off >>= 1) scnt += __shfl_down_sync(0xffffffffu, scnt, off);
    if (lane == 0 && scnt) atomicAdd(counter, (unsigned long long)scnt);
}

// ---------------- write the 4 spike-rate scalars ----------------
__global__ void finalize_kernel(float* __restrict__ out, long long out_size) {
    if (out_size >= (long long)BTND + 4) {
        out[BTND+0] = (float)((double)g_cnt[0] / 4194304.0);   // r_lif1
        out[BTND+1] = (float)((double)g_cnt[1] / 16777216.0);  // r_attn
        out[BTND+2] = (float)((double)g_cnt[2] / 4194304.0);   // r_lif2
        out[BTND+3] = (float)((double)g_cnt[3] / 16777216.0);  // r_ffn
    }
}

// ---------------- host launcher ----------------
extern "C" void kernel_launch(void* const* d_in, const int* in_sizes, int n_in,
                              void* d_out, int out_size) {
    const float* x  = (const float*)d_in[0];
    const float* g1 = (const float*)d_in[1];
    const float* b1 = (const float*)d_in[2];
    const float* wq = (const float*)d_in[3];
    const float* wk = (const float*)d_in[4];
    const float* wv = (const float*)d_in[5];
    const float* wo = (const float*)d_in[6];
    const float* g2 = (const float*)d_in[7];
    const float* b2 = (const float*)d_in[8];
    const float* w1 = (const float*)d_in[9];
    const float* w2 = (const float*)d_in[10];
    float* out = (float*)d_out;

    __half *s1h, *qkvh, *qkvl, *sah, *aoh, *aol, *s2h, *hsh;
    __half *wqkvh,*wqkvl,*woh,*wol,*w1h,*w1l,*w2h;
    float *xm, *hid;
    unsigned long long* cnt;
    cudaGetSymbolAddress((void**)&s1h,  g_s1h);
    cudaGetSymbolAddress((void**)&qkvh, g_qkvh); cudaGetSymbolAddress((void**)&qkvl, g_qkvl);
    cudaGetSymbolAddress((void**)&sah,  g_sah);
    cudaGetSymbolAddress((void**)&aoh,  g_aoh);  cudaGetSymbolAddress((void**)&aol,  g_aol);
    cudaGetSymbolAddress((void**)&xm,   g_xm);
    cudaGetSymbolAddress((void**)&s2h,  g_s2h);
    cudaGetSymbolAddress((void**)&hid,  g_hid);
    cudaGetSymbolAddress((void**)&hsh,  g_hsh);
    cudaGetSymbolAddress((void**)&wqkvh,g_wqkvh);cudaGetSymbolAddress((void**)&wqkvl,g_wqkvl);
    cudaGetSymbolAddress((void**)&woh,  g_woh);  cudaGetSymbolAddress((void**)&wol,  g_wol);
    cudaGetSymbolAddress((void**)&w1h,  g_w1h);  cudaGetSymbolAddress((void**)&w1l,  g_w1l);
    cudaGetSymbolAddress((void**)&w2h,  g_w2h);
    cudaGetSymbolAddress((void**)&cnt,  g_cnt);

    const int SMEM_QKV = 2*(128*72 + 2*64*136) * 2;          // 106496
    const int SMEM_AO  = 2*(128*72 + 2*64*72) * 2;           // 73728
    const int SMEM_WO  = 1*(2*128*72 + 2*64*136) * 2;        // 71680
    const int SMEM_W1  = SMEM_QKV;
    const int SMEM_W2  = 2*(128*72 + 64*136) * 2;            // 71680
    const int SMEM_SL  = 2*(4*128*72) * 2;                   // 147456 (scores+LIF)

    cudaFuncSetAttribute(mma_gemm<false,true ,true ,true ,false,128,2>, cudaFuncAttributeMaxDynamicSharedMemorySize, SMEM_QKV);
    cudaFuncSetAttribute(mma_gemm<false,true ,true ,true ,false,64 ,2>, cudaFuncAttributeMaxDynamicSharedMemorySize, SMEM_AO);
    cudaFuncSetAttribute(mma_gemm<true ,true ,true ,false,true ,128,1>, cudaFuncAttributeMaxDynamicSharedMemorySize, SMEM_WO);
    cudaFuncSetAttribute(mma_gemm<false,true ,true ,false,false,128,2>, cudaFuncAttributeMaxDynamicSharedMemorySize, SMEM_W1);
    cudaFuncSetAttribute(mma_gemm<false,false,true ,false,true ,128,2>, cudaFuncAttributeMaxDynamicSharedMemorySize, SMEM_W2);
    cudaFuncSetAttribute(scores_lif_kernel, cudaFuncAttributeMaxDynamicSharedMemorySize, SMEM_SL);

    zero_cnt_kernel<<<1, 32>>>();

    split_all_kernel<<<(3*Dd*Dd + Dd*Dd + 2*Dd*HIDd + 255)/256, 256>>>(
        wq, wk, wv, wo, w1, w2,
        wqkvh, wqkvl, woh, wol, w1h, w1l, w2h);

    // ---- attention branch ----
    ln_lif_kernel<<<Bb*Nn, 512>>>(x, g1, b1, s1h, cnt + 0);

    mma_gemm<false,true,true,true,false,128,2><<<dim3(QKVW/128, BTN/128), 256, SMEM_QKV>>>(
        s1h, nullptr, wqkvh, wqkvl, nullptr, nullptr, qkvh, qkvl,
        Dd, Dd, QKVW, QKVW, 1, 0,0, 0,0, 0,0, 1.f);

    // fused scores + attention LIF (writes binary spikes directly)
    scores_lif_kernel<<<dim3(Nn/128, Nn/128, Bb*Hh), 512, SMEM_SL>>>(
        qkvh, qkvl, sah, cnt + 1);

    mma_gemm<false,true,true,true,false,64,2><<<dim3(DHh/64, Nn/128, Bb*Tt*Hh), 256, SMEM_AO>>>(
        sah, nullptr, qkvh + 2*Dd, qkvl + 2*Dd, nullptr, nullptr, aoh, aol,
        Nn, Nn, QKVW, Dd,
        Hh, (long long)Hh*Nn*Nn, (long long)Nn*Nn,
        (long long)Nn*QKVW, 64LL, (long long)Nn*Dd, 64LL, 1.f);

    mma_gemm<true,true,true,false,true,128,1><<<dim3(Dd/128, BTN/128), 256, SMEM_WO>>>(
        aoh, aol, woh, wol, x, xm, nullptr, nullptr,
        Dd, Dd, Dd, Dd, 1, 0,0, 0,0, 0,0, 1.f);

    // ---- MLP branch ----
    ln_lif_kernel<<<Bb*Nn, 512>>>(xm, g2, b2, s2h, cnt + 2);

    mma_gemm<false,true,true,false,false,128,2><<<dim3(HIDd/128, BTN/128), 256, SMEM_W1>>>(
        s2h, nullptr, w1h, w1l, nullptr, hid, nullptr, nullptr,
        Dd, Dd, HIDd, HIDd, 1, 0,0, 0,0, 0,0, 1.f);

    lif_time_kernel<<<16384, 256>>>(hid, hsh, Nn*HIDd, 1.0f, cnt + 3);

    mma_gemm<false,false,true,false,true,128,2><<<dim3(Dd/128, BTN/128), 256, SMEM_W2>>>(
        hsh, nullptr, w2h, nullptr, xm, out, nullptr, nullptr,
        HIDd, HIDd, Dd, Dd, 1, 0,0, 0,0, 0,0, 1.f);

    finalize_kernel<<<1, 1>>>(out, (long long)out_size);
}